// round 3
// baseline (speedup 1.0000x reference)
#include <cuda_runtime.h>
#include <math.h>

#define NMAT 100000
#define NELEM 118
#define HIDC 128
#define NH 8
#define OUTC 64

// ---------------- scratch (device globals; no runtime alloc) ----------------
__device__ float    g_h_mat[NMAT * HIDC];          // 51.2 MB
__device__ float    g_h_elem[NELEM * HIDC];
__device__ float    g_adst_em[NMAT * NH];
__device__ float    g_asrc_mm[NMAT * NH];
__device__ float    g_adst_mm[NMAT * NH];
__device__ float    g_asrc_em[NELEM * NH];
__device__ unsigned g_amax[2][NMAT * NH];          // ordered-uint encoded float max
__device__ float    g_den[2][NMAT * NH];
__device__ float    g_o[2][NMAT * HIDC];           // 102.4 MB (accum -> finalized o_em/o_mm)
__device__ double   g_colsum[2][HIDC];
__device__ float    g_attn[2];

// monotonic float<->uint encoding for atomicMax on floats
__device__ __forceinline__ unsigned fenc(float f) {
    unsigned u = __float_as_uint(f);
    return (u & 0x80000000u) ? ~u : (u | 0x80000000u);
}
__device__ __forceinline__ float fdec(unsigned k) {
    return __uint_as_float((k & 0x80000000u) ? (k & 0x7fffffffu) : ~k);
}

// ---------------- init: zero accumulators ----------------
__global__ void k_init() {
    int i = blockIdx.x * blockDim.x + threadIdx.x;
    int stride = gridDim.x * blockDim.x;
    float4 z = make_float4(0.f, 0.f, 0.f, 0.f);
    uint4 zu = make_uint4(0u, 0u, 0u, 0u);
    float4* o4 = (float4*)g_o;
    for (int j = i; j < 2 * NMAT * 32; j += stride) o4[j] = z;
    float4* d4 = (float4*)g_den;
    uint4*  a4 = (uint4*)g_amax;
    for (int j = i; j < 2 * NMAT * 2; j += stride) { d4[j] = z; a4[j] = zu; }
    if (i < 2 * HIDC) ((double*)g_colsum)[i] = 0.0;
}

// ---------------- fused 128x128 NT GEMM (tile 64 nodes x 128 ch, K=128) -----
// mode 0: Y = X @ W^T + b  -> g_h_mat
// mode 1/2: colsum[m] += sum_n tanh(o[m] @ Wk^T + bk)   (m = mode-1)
#define GEMM_SMEM ((128 * 132 + 64 * 132 + 128) * 4)

__global__ __launch_bounds__(256) void k_gemm128(
    const float* __restrict__ Xarg, const float* __restrict__ W,
    const float* __restrict__ bias, int N, int mode)
{
    extern __shared__ float sm[];
    float* ws = sm;                    // 128 x 132
    float* xs = sm + 128 * 132;        // 64 x 132
    float* cs = xs + 64 * 132;         // 128
    const float* X = (mode == 0) ? Xarg : (const float*)g_o[mode - 1];
    int n0 = blockIdx.x * 64;
    int t = threadIdx.x;

    for (int i = t; i < 128 * 32; i += 256) {
        int r = i >> 5, c4 = i & 31;
        float4 v = ((const float4*)W)[i];
        *(float4*)&ws[r * 132 + c4 * 4] = v;
    }
    for (int i = t; i < 64 * 32; i += 256) {
        int r = i >> 5, c4 = i & 31;
        int n = n0 + r;
        float4 v = make_float4(0.f, 0.f, 0.f, 0.f);
        if (n < N) v = ((const float4*)X)[n * 32 + c4];
        *(float4*)&xs[r * 132 + c4 * 4] = v;
    }
    if (mode != 0 && t < 128) cs[t] = 0.f;
    __syncthreads();

    int cg = t & 15, ng = t >> 4;
    float acc[4][8];
#pragma unroll
    for (int i = 0; i < 4; i++)
#pragma unroll
        for (int j = 0; j < 8; j++) acc[i][j] = 0.f;

    for (int k = 0; k < 128; k += 4) {
        float4 xv[4], wv[8];
#pragma unroll
        for (int i = 0; i < 4; i++) xv[i] = *(float4*)&xs[(ng + 16 * i) * 132 + k];
#pragma unroll
        for (int j = 0; j < 8; j++) wv[j] = *(float4*)&ws[(cg + 16 * j) * 132 + k];
#pragma unroll
        for (int i = 0; i < 4; i++)
#pragma unroll
            for (int j = 0; j < 8; j++)
                acc[i][j] += xv[i].x * wv[j].x + xv[i].y * wv[j].y +
                             xv[i].z * wv[j].z + xv[i].w * wv[j].w;
    }

    float bb[8];
#pragma unroll
    for (int j = 0; j < 8; j++) bb[j] = bias[cg + 16 * j];

    if (mode == 0) {
#pragma unroll
        for (int i = 0; i < 4; i++) {
            int n = n0 + ng + 16 * i;
            if (n < N) {
#pragma unroll
                for (int j = 0; j < 8; j++)
                    g_h_mat[n * HIDC + cg + 16 * j] = acc[i][j] + bb[j];
            }
        }
    } else {
#pragma unroll
        for (int j = 0; j < 8; j++) {
            float s = 0.f;
#pragma unroll
            for (int i = 0; i < 4; i++) {
                int n = n0 + ng + 16 * i;
                if (n < N) s += tanhf(acc[i][j] + bb[j]);
            }
            atomicAdd(&cs[cg + 16 * j], s);
        }
        __syncthreads();
        if (t < 128) atomicAdd(&g_colsum[mode - 1][t], (double)cs[t]);
    }
}

// ---------------- elem projection (tiny: 118 x 128, K=64) ----------------
__global__ void k_proj_elem(const float* __restrict__ x, const float* __restrict__ W,
                            const float* __restrict__ b)
{
    int i = blockIdx.x * blockDim.x + threadIdx.x;
    if (i >= NELEM * HIDC) return;
    int n = i >> 7, c = i & 127;
    float acc = b[c];
    const float* xr = x + n * 64;
    const float* wr = W + c * 64;
#pragma unroll 16
    for (int k = 0; k < 64; k++) acc += xr[k] * wr[k];
    g_h_elem[i] = acc;
}

// ---------------- per-node attention coefficients ----------------
__global__ void k_alphas_mat(const float* __restrict__ a_de,
                             const float* __restrict__ a_sm,
                             const float* __restrict__ a_dm)
{
    int i = blockIdx.x * blockDim.x + threadIdx.x;
    if (i >= NMAT * NH) return;
    int h = i & 7;
    const float4* hp = (const float4*)(g_h_mat + i * 16);   // i*16 == n*128 + h*16
    float s1 = 0.f, s2 = 0.f, s3 = 0.f;
#pragma unroll
    for (int d4 = 0; d4 < 4; d4++) {
        float4 v  = hp[d4];
        float4 w1 = __ldg(&((const float4*)a_de)[h * 4 + d4]);
        float4 w2 = __ldg(&((const float4*)a_sm)[h * 4 + d4]);
        float4 w3 = __ldg(&((const float4*)a_dm)[h * 4 + d4]);
        s1 += v.x * w1.x + v.y * w1.y + v.z * w1.z + v.w * w1.w;
        s2 += v.x * w2.x + v.y * w2.y + v.z * w2.z + v.w * w2.w;
        s3 += v.x * w3.x + v.y * w3.y + v.z * w3.z + v.w * w3.w;
    }
    g_adst_em[i] = s1; g_asrc_mm[i] = s2; g_adst_mm[i] = s3;
}

__global__ void k_alphas_elem(const float* __restrict__ a_se)
{
    int i = blockIdx.x * blockDim.x + threadIdx.x;
    if (i >= NELEM * NH) return;
    int h = i & 7;
    const float4* hp = (const float4*)(g_h_elem + i * 16);
    float s = 0.f;
#pragma unroll
    for (int d4 = 0; d4 < 4; d4++) {
        float4 v = hp[d4];
        float4 w = __ldg(&((const float4*)a_se)[h * 4 + d4]);
        s += v.x * w.x + v.y * w.y + v.z * w.z + v.w * w.w;
    }
    g_asrc_em[i] = s;
}

// ---------------- edge pass A: segment max of leaky-relu(alpha) ----------------
__global__ void k_edge_max(const int* __restrict__ src, const int* __restrict__ dst,
                           int E, int type)
{
    int e = blockIdx.x * blockDim.x + threadIdx.x;
    if (e >= E) return;
    int s = src[e], d = dst[e];
    const float* as = (type == 0 ? g_asrc_em : g_asrc_mm) + s * 8;
    const float* ad = (type == 0 ? g_adst_em : g_adst_mm) + d * 8;
    unsigned* am = g_amax[type] + d * 8;
    float4 a0 = *(const float4*)as, a1 = *(const float4*)(as + 4);
    float4 b0 = *(const float4*)ad, b1 = *(const float4*)(ad + 4);
    float al[8] = {a0.x + b0.x, a0.y + b0.y, a0.z + b0.z, a0.w + b0.w,
                   a1.x + b1.x, a1.y + b1.y, a1.z + b1.z, a1.w + b1.w};
#pragma unroll
    for (int h = 0; h < 8; h++) {
        float a = al[h];
        a = a > 0.f ? a : 0.2f * a;
        atomicMax(am + h, fenc(a));
    }
}

// ---------------- edge pass C: fused denominator + unnormalized aggregate ----
// warp per edge: lanes cover the 128 channels (lane*4 .. lane*4+3), head = lane/4
__global__ void k_edge_acc(const int* __restrict__ src, const int* __restrict__ dst,
                           int E, int type)
{
    int gw = (blockIdx.x * blockDim.x + threadIdx.x) >> 5;
    int lane = threadIdx.x & 31;
    if (gw >= E) return;
    int s = src[gw], d = dst[gw];
    int h = lane >> 2;
    const float* as   = (type == 0 ? g_asrc_em : g_asrc_mm);
    const float* ad   = (type == 0 ? g_adst_em : g_adst_mm);
    const float* xsrc = (type == 0 ? g_h_elem  : g_h_mat);
    float a = as[s * 8 + h] + ad[d * 8 + h];
    a = a > 0.f ? a : 0.2f * a;
    float mx = fdec(g_amax[type][d * 8 + h]);
    float ex = __expf(a - mx);
    if ((lane & 3) == 0) atomicAdd(&g_den[type][d * 8 + h], ex);
    float4 xv = *(const float4*)(xsrc + s * 128 + lane * 4);
    float4 o = make_float4(xv.x * ex, xv.y * ex, xv.z * ex, xv.w * ex);
    atomicAdd((float4*)(g_o[type] + d * 128 + lane * 4), o);
}

// ---------------- finalize: o = relu(acc / (den + 1e-16)) ----------------
__global__ void k_finalize()
{
    int i = blockIdx.x * blockDim.x + threadIdx.x;
    if (i >= 2 * NMAT * 32) return;
    int type = i / (NMAT * 32);
    int r = i - type * (NMAT * 32);
    int n = r >> 5, c4 = r & 31;
    float dn = g_den[type][n * 8 + (c4 >> 2)] + 1e-16f;
    float inv = 1.f / dn;
    float4* p = (float4*)(g_o[type] + n * 128 + c4 * 4);
    float4 v = *p;
    v.x = fmaxf(v.x * inv, 0.f);
    v.y = fmaxf(v.y * inv, 0.f);
    v.z = fmaxf(v.z * inv, 0.f);
    v.w = fmaxf(v.w * inv, 0.f);
    *p = v;
}

// ---------------- semantic attention over 2 metapaths ----------------
__global__ void k_semantic(const float* __restrict__ q)
{
    int t = threadIdx.x;  // 128
    float p0 = q[t] * (float)(g_colsum[0][t] * (1.0 / NMAT));
    float p1 = q[t] * (float)(g_colsum[1][t] * (1.0 / NMAT));
    for (int off = 16; off; off >>= 1) {
        p0 += __shfl_down_sync(0xffffffffu, p0, off);
        p1 += __shfl_down_sync(0xffffffffu, p1, off);
    }
    __shared__ float red[8];
    int w = t >> 5, l = t & 31;
    if (l == 0) { red[w * 2] = p0; red[w * 2 + 1] = p1; }
    __syncthreads();
    if (t == 0) {
        float s0 = red[0] + red[2] + red[4] + red[6];
        float s1 = red[1] + red[3] + red[5] + red[7];
        float m = fmaxf(s0, s1);
        float e0 = expf(s0 - m), e1 = expf(s1 - m);
        float inv = 1.f / (e0 + e1);
        g_attn[0] = e0 * inv; g_attn[1] = e1 * inv;
    }
}

// ---------------- final: out = (a0*o_em + a1*o_mm) @ Wl^T + bl ----------------
#define FIN_SMEM ((64 * 132 + 64 * 132) * 4)

__global__ __launch_bounds__(256) void k_final(
    const float* __restrict__ Wl, const float* __restrict__ bl,
    float* __restrict__ out, int N)
{
    extern __shared__ float sm[];
    float* ws = sm;                 // 64 x 132
    float* xs = sm + 64 * 132;      // 64 x 132
    float a0 = g_attn[0], a1 = g_attn[1];
    int n0 = blockIdx.x * 64;
    int t = threadIdx.x;

    for (int i = t; i < 64 * 32; i += 256) {
        int r = i >> 5, c4 = i & 31;
        *(float4*)&ws[r * 132 + c4 * 4] = ((const float4*)Wl)[i];
    }
    for (int i = t; i < 64 * 32; i += 256) {
        int r = i >> 5, c4 = i & 31;
        int n = n0 + r;
        float4 v = make_float4(0.f, 0.f, 0.f, 0.f);
        if (n < N) {
            float4 u = ((const float4*)g_o[0])[n * 32 + c4];
            float4 w = ((const float4*)g_o[1])[n * 32 + c4];
            v.x = a0 * u.x + a1 * w.x;
            v.y = a0 * u.y + a1 * w.y;
            v.z = a0 * u.z + a1 * w.z;
            v.w = a0 * u.w + a1 * w.w;
        }
        *(float4*)&xs[r * 132 + c4 * 4] = v;
    }
    __syncthreads();

    int cg = t & 15, ng = t >> 4;
    float acc[4][4];
#pragma unroll
    for (int i = 0; i < 4; i++)
#pragma unroll
        for (int j = 0; j < 4; j++) acc[i][j] = 0.f;

    for (int k = 0; k < 128; k += 4) {
        float4 xv[4], wv[4];
#pragma unroll
        for (int i = 0; i < 4; i++) xv[i] = *(float4*)&xs[(ng + 16 * i) * 132 + k];
#pragma unroll
        for (int j = 0; j < 4; j++) wv[j] = *(float4*)&ws[(cg + 16 * j) * 132 + k];
#pragma unroll
        for (int i = 0; i < 4; i++)
#pragma unroll
            for (int j = 0; j < 4; j++)
                acc[i][j] += xv[i].x * wv[j].x + xv[i].y * wv[j].y +
                             xv[i].z * wv[j].z + xv[i].w * wv[j].w;
    }
#pragma unroll
    for (int i = 0; i < 4; i++) {
        int n = n0 + ng + 16 * i;
        if (n < N) {
#pragma unroll
            for (int j = 0; j < 4; j++)
                out[n * OUTC + cg + 16 * j] = acc[i][j] + bl[cg + 16 * j];
        }
    }
}

// ---------------- launch ----------------
extern "C" void kernel_launch(void* const* d_in, const int* in_sizes, int n_in,
                              void* d_out, int out_size)
{
    const float* x_mat    = (const float*)d_in[0];
    const float* x_elem   = (const float*)d_in[1];
    const float* Wpm      = (const float*)d_in[2];
    const float* bpm      = (const float*)d_in[3];
    const float* Wpe      = (const float*)d_in[4];
    const float* bpe      = (const float*)d_in[5];
    const float* a_src_em = (const float*)d_in[6];
    const float* a_dst_em = (const float*)d_in[7];
    const float* a_src_mm = (const float*)d_in[8];
    const float* a_dst_mm = (const float*)d_in[9];
    const float* Wk       = (const float*)d_in[10];
    const float* bk       = (const float*)d_in[11];
    const float* q        = (const float*)d_in[12];
    const float* Wl       = (const float*)d_in[13];
    const float* bl       = (const float*)d_in[14];
    const int*   src_em   = (const int*)d_in[15];
    const int*   dst_em   = (const int*)d_in[16];
    const int*   src_mm   = (const int*)d_in[17];
    const int*   dst_mm   = (const int*)d_in[18];
    float* out = (float*)d_out;
    int E_em = in_sizes[15];
    int E_mm = in_sizes[17];

    cudaFuncSetAttribute(k_gemm128, cudaFuncAttributeMaxDynamicSharedMemorySize, GEMM_SMEM);
    cudaFuncSetAttribute(k_final,   cudaFuncAttributeMaxDynamicSharedMemorySize, FIN_SMEM);

    int gb = (NMAT + 63) / 64;

    k_init<<<2048, 256>>>();
    k_gemm128<<<gb, 256, GEMM_SMEM>>>(x_mat, Wpm, bpm, NMAT, 0);
    k_proj_elem<<<(NELEM * HIDC + 255) / 256, 256>>>(x_elem, Wpe, bpe);
    k_alphas_mat<<<(NMAT * NH + 255) / 256, 256>>>(a_dst_em, a_src_mm, a_dst_mm);
    k_alphas_elem<<<(NELEM * NH + 255) / 256, 256>>>(a_src_em);
    k_edge_max<<<(E_em + 255) / 256, 256>>>(src_em, dst_em, E_em, 0);
    k_edge_max<<<(E_mm + 255) / 256, 256>>>(src_mm, dst_mm, E_mm, 1);
    k_edge_acc<<<(E_em + 7) / 8, 256>>>(src_em, dst_em, E_em, 0);
    k_edge_acc<<<(E_mm + 7) / 8, 256>>>(src_mm, dst_mm, E_mm, 1);
    k_finalize<<<(2 * NMAT * 32 + 255) / 256, 256>>>();
    k_gemm128<<<gb, 256, GEMM_SMEM>>>(nullptr, Wk, bk, NMAT, 1);
    k_gemm128<<<gb, 256, GEMM_SMEM>>>(nullptr, Wk, bk, NMAT, 2);
    k_semantic<<<1, 128>>>(q);
    k_final<<<gb, 256, FIN_SMEM>>>(Wl, bl, out, NMAT);
}

// round 6
// speedup vs baseline: 1.5023x; 1.5023x over previous
#include <cuda_runtime.h>
#include <math.h>

#define NMAT 100000
#define NELEM 118
#define HIDC 128
#define NH 8
#define OUTC 64

// ---------------- scratch (device globals; no runtime alloc) ----------------
__device__ float    g_h_mat[NMAT * HIDC];          // 51.2 MB
__device__ float    g_h_elem[NELEM * HIDC];
__device__ float    g_adst_em[NMAT * NH];
__device__ float    g_asrc_mm[NMAT * NH];
__device__ float    g_adst_mm[NMAT * NH];
__device__ float    g_asrc_em[NELEM * NH];
__device__ float    g_den[2][NMAT * NH];           // exp-sum, then inverted in place
__device__ float    g_o[2][NMAT * HIDC];           // 102.4 MB unnormalized accumulators
__device__ double   g_colsum[2][HIDC];
__device__ float    g_attn[2];

// packed f32x2 FMA (ptxas never emits FFMA2 from C++; PTX fma.rn.f32x2 only)
#define FMA2(acc, a, b) \
    asm("fma.rn.f32x2 %0, %1, %2, %0;" : "+l"(acc) : "l"(a), "l"(b))

union U2 { unsigned long long u; float2 f; };

// ---------------- init: zero accumulators ----------------
__global__ void k_init() {
    int i = blockIdx.x * blockDim.x + threadIdx.x;
    int stride = gridDim.x * blockDim.x;
    float4 z = make_float4(0.f, 0.f, 0.f, 0.f);
    float4* o4 = (float4*)g_o;
    for (int j = i; j < 2 * NMAT * 32; j += stride) o4[j] = z;
    float4* d4 = (float4*)g_den;
    for (int j = i; j < 2 * NMAT * 2; j += stride) d4[j] = z;
    if (i < 2 * HIDC) ((double*)g_colsum)[i] = 0.0;
}

// ---------------- fused 128x128 NT GEMM (tile 64 nodes x 128 ch, K=128) -----
// mode 0: Y = X @ W^T + b  -> g_h_mat
// mode 1/2: colsum[m] += sum_n tanh(relu(o[m]*inv) @ Wk^T + bk)   (m = mode-1)
#define GEMM_SMEM ((128 * 132 + 64 * 132 + 128) * 4)

__global__ __launch_bounds__(256) void k_gemm128(
    const float* __restrict__ Xarg, const float* __restrict__ W,
    const float* __restrict__ bias, int N, int mode)
{
    extern __shared__ float sm[];
    float* ws = sm;                    // 128 x 132
    float* xs = sm + 128 * 132;        // 64 x 132
    float* cs = xs + 64 * 132;         // 128
    int n0 = blockIdx.x * 64;
    int t = threadIdx.x;

    for (int i = t; i < 128 * 32; i += 256) {
        int r = i >> 5, c4 = i & 31;
        float4 v = ((const float4*)W)[i];
        *(float4*)&ws[r * 132 + c4 * 4] = v;
    }
    if (mode == 0) {
        for (int i = t; i < 64 * 32; i += 256) {
            int r = i >> 5, c4 = i & 31;
            int n = n0 + r;
            float4 v = make_float4(0.f, 0.f, 0.f, 0.f);
            if (n < N) v = ((const float4*)Xarg)[n * 32 + c4];
            *(float4*)&xs[r * 132 + c4 * 4] = v;
        }
    } else {
        int m = mode - 1;
        for (int i = t; i < 64 * 32; i += 256) {
            int r = i >> 5, c4 = i & 31;
            int n = n0 + r;
            float4 v = make_float4(0.f, 0.f, 0.f, 0.f);
            if (n < N) {
                float4 u = ((const float4*)g_o[m])[n * 32 + c4];
                float inv = g_den[m][n * 8 + (c4 >> 2)];   // already inverted
                v.x = fmaxf(u.x * inv, 0.f);
                v.y = fmaxf(u.y * inv, 0.f);
                v.z = fmaxf(u.z * inv, 0.f);
                v.w = fmaxf(u.w * inv, 0.f);
            }
            *(float4*)&xs[r * 132 + c4 * 4] = v;
        }
        if (t < 128) cs[t] = 0.f;
    }
    __syncthreads();

    int cg = t & 15, ng = t >> 4;
    unsigned long long acc[4][8];
#pragma unroll
    for (int i = 0; i < 4; i++)
#pragma unroll
        for (int j = 0; j < 8; j++) acc[i][j] = 0ull;

    for (int k = 0; k < 128; k += 4) {
        ulonglong2 xv[4], wv[8];
#pragma unroll
        for (int i = 0; i < 4; i++)
            xv[i] = *(const ulonglong2*)&xs[(ng + 16 * i) * 132 + k];
#pragma unroll
        for (int j = 0; j < 8; j++)
            wv[j] = *(const ulonglong2*)&ws[(cg + 16 * j) * 132 + k];
#pragma unroll
        for (int i = 0; i < 4; i++)
#pragma unroll
            for (int j = 0; j < 8; j++) {
                FMA2(acc[i][j], xv[i].x, wv[j].x);
                FMA2(acc[i][j], xv[i].y, wv[j].y);
            }
    }

    float bb[8];
#pragma unroll
    for (int j = 0; j < 8; j++) bb[j] = bias[cg + 16 * j];

    if (mode == 0) {
#pragma unroll
        for (int i = 0; i < 4; i++) {
            int n = n0 + ng + 16 * i;
            if (n < N) {
#pragma unroll
                for (int j = 0; j < 8; j++) {
                    U2 u; u.u = acc[i][j];
                    g_h_mat[n * HIDC + cg + 16 * j] = u.f.x + u.f.y + bb[j];
                }
            }
        }
    } else {
#pragma unroll
        for (int j = 0; j < 8; j++) {
            float s = 0.f;
#pragma unroll
            for (int i = 0; i < 4; i++) {
                int n = n0 + ng + 16 * i;
                if (n < N) {
                    U2 u; u.u = acc[i][j];
                    s += tanhf(u.f.x + u.f.y + bb[j]);
                }
            }
            atomicAdd(&cs[cg + 16 * j], s);
        }
        __syncthreads();
        if (t < 128) atomicAdd(&g_colsum[mode - 1][t], (double)cs[t]);
    }
}

// ---------------- elem projection (tiny: 118 x 128, K=64) ----------------
__global__ void k_proj_elem(const float* __restrict__ x, const float* __restrict__ W,
                            const float* __restrict__ b)
{
    int i = blockIdx.x * blockDim.x + threadIdx.x;
    if (i >= NELEM * HIDC) return;
    int n = i >> 7, c = i & 127;
    float acc = b[c];
    const float* xr = x + n * 64;
    const float* wr = W + c * 64;
#pragma unroll 16
    for (int k = 0; k < 64; k++) acc += xr[k] * wr[k];
    g_h_elem[i] = acc;
}

// ---------------- per-node attention coefficients (a-vectors in smem) -------
__global__ __launch_bounds__(256) void k_alphas_mat(
    const float* __restrict__ a_de, const float* __restrict__ a_sm,
    const float* __restrict__ a_dm)
{
    __shared__ float4 sa[96];   // 3 vecs x (8 heads x 4 float4)
    int t = threadIdx.x;
    if (t < 32)       sa[t]      = ((const float4*)a_de)[t];
    else if (t < 64)  sa[t]      = ((const float4*)a_sm)[t - 32];
    else if (t < 96)  sa[t]      = ((const float4*)a_dm)[t - 64];
    __syncthreads();

    int i = blockIdx.x * blockDim.x + t;
    if (i >= NMAT * NH) return;
    int h = i & 7;
    const float4* hp = (const float4*)(g_h_mat + i * 16);   // i*16 == n*128 + h*16
    float s1 = 0.f, s2 = 0.f, s3 = 0.f;
#pragma unroll
    for (int d4 = 0; d4 < 4; d4++) {
        float4 v  = hp[d4];
        float4 w1 = sa[h * 4 + d4];
        float4 w2 = sa[32 + h * 4 + d4];
        float4 w3 = sa[64 + h * 4 + d4];
        s1 += v.x * w1.x + v.y * w1.y + v.z * w1.z + v.w * w1.w;
        s2 += v.x * w2.x + v.y * w2.y + v.z * w2.z + v.w * w2.w;
        s3 += v.x * w3.x + v.y * w3.y + v.z * w3.z + v.w * w3.w;
    }
    g_adst_em[i] = s1; g_asrc_mm[i] = s2; g_adst_mm[i] = s3;
}

__global__ void k_alphas_elem(const float* __restrict__ a_se)
{
    int i = blockIdx.x * blockDim.x + threadIdx.x;
    if (i >= NELEM * NH) return;
    int h = i & 7;
    const float4* hp = (const float4*)(g_h_elem + i * 16);
    float s = 0.f;
#pragma unroll
    for (int d4 = 0; d4 < 4; d4++) {
        float4 v = hp[d4];
        float4 w = __ldg(&((const float4*)a_se)[h * 4 + d4]);
        s += v.x * w.x + v.y * w.y + v.z * w.z + v.w * w.w;
    }
    g_asrc_em[i] = s;
}

// ---------------- single edge pass: denominator + unnormalized aggregate ----
// softmax computed WITHOUT max subtraction: alpha ~ N(0, 0.65^2), max over 3M
// edges ~3.3, exp() <= ~30 -> safe in fp32; normalized weights identical.
// warp per edge: lanes cover the 128 channels, head = lane/4
__global__ __launch_bounds__(256) void k_edge_acc(
    const int* __restrict__ src, const int* __restrict__ dst, int E, int type)
{
    int lane = threadIdx.x & 31;
    int wstride = (gridDim.x * blockDim.x) >> 5;
    const float* as   = (type == 0 ? g_asrc_em : g_asrc_mm);
    const float* ad   = (type == 0 ? g_adst_em : g_adst_mm);
    const float* xsrc = (type == 0 ? g_h_elem  : g_h_mat);
    int h = lane >> 2;
    for (int e = (blockIdx.x * blockDim.x + threadIdx.x) >> 5; e < E; e += wstride) {
        int s = src[e], d = dst[e];
        float a = as[s * 8 + h] + ad[d * 8 + h];
        a = a > 0.f ? a : 0.2f * a;
        float ex = __expf(a);
        if ((lane & 3) == 0) atomicAdd(&g_den[type][d * 8 + h], ex);
        float4 xv = *(const float4*)(xsrc + s * 128 + lane * 4);
        float4 o = make_float4(xv.x * ex, xv.y * ex, xv.z * ex, xv.w * ex);
        atomicAdd((float4*)(g_o[type] + d * 128 + lane * 4), o);
    }
}

// ---------------- invert denominators in place ----------------
__global__ void k_inv()
{
    int i = blockIdx.x * blockDim.x + threadIdx.x;
    if (i >= 2 * NMAT * NH) return;
    ((float*)g_den)[i] = 1.f / (((float*)g_den)[i] + 1e-16f);
}

// ---------------- semantic attention over 2 metapaths ----------------
__global__ void k_semantic(const float* __restrict__ q)
{
    int t = threadIdx.x;  // 128
    float p0 = q[t] * (float)(g_colsum[0][t] * (1.0 / NMAT));
    float p1 = q[t] * (float)(g_colsum[1][t] * (1.0 / NMAT));
    for (int off = 16; off; off >>= 1) {
        p0 += __shfl_down_sync(0xffffffffu, p0, off);
        p1 += __shfl_down_sync(0xffffffffu, p1, off);
    }
    __shared__ float red[8];
    int w = t >> 5, l = t & 31;
    if (l == 0) { red[w * 2] = p0; red[w * 2 + 1] = p1; }
    __syncthreads();
    if (t == 0) {
        float s0 = red[0] + red[2] + red[4] + red[6];
        float s1 = red[1] + red[3] + red[5] + red[7];
        float m = fmaxf(s0, s1);
        float e0 = expf(s0 - m), e1 = expf(s1 - m);
        float inv = 1.f / (e0 + e1);
        g_attn[0] = e0 * inv; g_attn[1] = e1 * inv;
    }
}

// ---------------- final: out = (a0*relu(o_em*inv0) + a1*relu(o_mm*inv1)) @ Wl^T + bl
#define FIN_SMEM ((64 * 132 + 64 * 132) * 4)

__global__ __launch_bounds__(256) void k_final(
    const float* __restrict__ Wl, const float* __restrict__ bl,
    float* __restrict__ out, int N)
{
    extern __shared__ float sm[];
    float* ws = sm;                 // 64 x 132
    float* xs = sm + 64 * 132;      // 64 x 132
    float a0 = g_attn[0], a1 = g_attn[1];
    int n0 = blockIdx.x * 64;
    int t = threadIdx.x;

    for (int i = t; i < 64 * 32; i += 256) {
        int r = i >> 5, c4 = i & 31;
        *(float4*)&ws[r * 132 + c4 * 4] = ((const float4*)Wl)[i];
    }
    for (int i = t; i < 64 * 32; i += 256) {
        int r = i >> 5, c4 = i & 31;
        int n = n0 + r;
        float4 v = make_float4(0.f, 0.f, 0.f, 0.f);
        if (n < N) {
            float4 u = ((const float4*)g_o[0])[n * 32 + c4];
            float4 w = ((const float4*)g_o[1])[n * 32 + c4];
            float i0 = g_den[0][n * 8 + (c4 >> 2)];
            float i1 = g_den[1][n * 8 + (c4 >> 2)];
            v.x = a0 * fmaxf(u.x * i0, 0.f) + a1 * fmaxf(w.x * i1, 0.f);
            v.y = a0 * fmaxf(u.y * i0, 0.f) + a1 * fmaxf(w.y * i1, 0.f);
            v.z = a0 * fmaxf(u.z * i0, 0.f) + a1 * fmaxf(w.z * i1, 0.f);
            v.w = a0 * fmaxf(u.w * i0, 0.f) + a1 * fmaxf(w.w * i1, 0.f);
        }
        *(float4*)&xs[r * 132 + c4 * 4] = v;
    }
    __syncthreads();

    int cg = t & 15, ng = t >> 4;
    unsigned long long acc[4][4];
#pragma unroll
    for (int i = 0; i < 4; i++)
#pragma unroll
        for (int j = 0; j < 4; j++) acc[i][j] = 0ull;

    for (int k = 0; k < 128; k += 4) {
        ulonglong2 xv[4], wv[4];
#pragma unroll
        for (int i = 0; i < 4; i++)
            xv[i] = *(const ulonglong2*)&xs[(ng + 16 * i) * 132 + k];
#pragma unroll
        for (int j = 0; j < 4; j++)
            wv[j] = *(const ulonglong2*)&ws[(cg + 16 * j) * 132 + k];
#pragma unroll
        for (int i = 0; i < 4; i++)
#pragma unroll
            for (int j = 0; j < 4; j++) {
                FMA2(acc[i][j], xv[i].x, wv[j].x);
                FMA2(acc[i][j], xv[i].y, wv[j].y);
            }
    }
#pragma unroll
    for (int i = 0; i < 4; i++) {
        int n = n0 + ng + 16 * i;
        if (n < N) {
#pragma unroll
            for (int j = 0; j < 4; j++) {
                U2 u; u.u = acc[i][j];
                out[n * OUTC + cg + 16 * j] = u.f.x + u.f.y + bl[cg + 16 * j];
            }
        }
    }
}

// ---------------- launch ----------------
extern "C" void kernel_launch(void* const* d_in, const int* in_sizes, int n_in,
                              void* d_out, int out_size)
{
    const float* x_mat    = (const float*)d_in[0];
    const float* x_elem   = (const float*)d_in[1];
    const float* Wpm      = (const float*)d_in[2];
    const float* bpm      = (const float*)d_in[3];
    const float* Wpe      = (const float*)d_in[4];
    const float* bpe      = (const float*)d_in[5];
    const float* a_src_em = (const float*)d_in[6];
    const float* a_dst_em = (const float*)d_in[7];
    const float* a_src_mm = (const float*)d_in[8];
    const float* a_dst_mm = (const float*)d_in[9];
    const float* Wk       = (const float*)d_in[10];
    const float* bk       = (const float*)d_in[11];
    const float* q        = (const float*)d_in[12];
    const float* Wl       = (const float*)d_in[13];
    const float* bl       = (const float*)d_in[14];
    const int*   src_em   = (const int*)d_in[15];
    const int*   dst_em   = (const int*)d_in[16];
    const int*   src_mm   = (const int*)d_in[17];
    const int*   dst_mm   = (const int*)d_in[18];
    float* out = (float*)d_out;
    int E_em = in_sizes[15];
    int E_mm = in_sizes[17];

    cudaFuncSetAttribute(k_gemm128, cudaFuncAttributeMaxDynamicSharedMemorySize, GEMM_SMEM);
    cudaFuncSetAttribute(k_final,   cudaFuncAttributeMaxDynamicSharedMemorySize, FIN_SMEM);

    int gb = (NMAT + 63) / 64;
    int eg = 148 * 8;   // capped grid for edge passes (grid-stride, 8 warps/CTA x 8 blocks/SM-ish)

    k_init<<<2048, 256>>>();
    k_gemm128<<<gb, 256, GEMM_SMEM>>>(x_mat, Wpm, bpm, NMAT, 0);
    k_proj_elem<<<(NELEM * HIDC + 255) / 256, 256>>>(x_elem, Wpe, bpe);
    k_alphas_mat<<<(NMAT * NH + 255) / 256, 256>>>(a_dst_em, a_src_mm, a_dst_mm);
    k_alphas_elem<<<(NELEM * NH + 255) / 256, 256>>>(a_src_em);
    k_edge_acc<<<eg, 256>>>(src_em, dst_em, E_em, 0);
    k_edge_acc<<<eg, 256>>>(src_mm, dst_mm, E_mm, 1);
    k_inv<<<(2 * NMAT * NH + 255) / 256, 256>>>();
    k_gemm128<<<gb, 256, GEMM_SMEM>>>(nullptr, Wk, bk, NMAT, 1);
    k_gemm128<<<gb, 256, GEMM_SMEM>>>(nullptr, Wk, bk, NMAT, 2);
    k_semantic<<<1, 128>>>(q);
    k_final<<<gb, 256, FIN_SMEM>>>(Wl, bl, out, NMAT);
}

// round 8
// speedup vs baseline: 1.8564x; 1.2357x over previous
#include <cuda_runtime.h>
#include <math.h>

#define NMAT 100000
#define NELEM 118
#define HIDC 128
#define NH 8
#define OUTC 64
#define SCAN_N (2 * NMAT)
#define NB ((SCAN_N + 1023) / 1024)      // 196 scan blocks
#define MAXE 3200000

// ---------------- scratch (device globals; no runtime alloc) ----------------
__device__ float    g_h_mat[NMAT * HIDC];          // 51.2 MB
__device__ float    g_h_elem[NELEM * HIDC];
__device__ float    g_adst_em[NMAT * NH];
__device__ float    g_asrc_mm[NMAT * NH];
__device__ float    g_adst_mm[NMAT * NH];
__device__ float    g_asrc_em[NELEM * NH];
__device__ float    g_o[2][NMAT * HIDC];           // final normalized o_em/o_mm
__device__ double   g_colsum[2][HIDC];
__device__ float    g_attn[2];
// CSR build
__device__ int      g_cnt[SCAN_N];                 // per (type,dst) degree
__device__ int      g_base[SCAN_N];                // exclusive prefix
__device__ int      g_cur[SCAN_N];                 // scatter cursor
__device__ int      g_bsum[NB];
__device__ int      g_sorted[MAXE];                // src ids sorted by (type,dst)

// packed f32x2 FMA (ptxas never emits FFMA2 from C++; PTX fma.rn.f32x2 only)
#define FMA2(acc, a, b) \
    asm("fma.rn.f32x2 %0, %1, %2, %0;" : "+l"(acc) : "l"(a), "l"(b))

union U2 { unsigned long long u; float2 f; };

// ---------------- init: zero degree counters + colsum ----------------
__global__ void k_init() {
    int i = blockIdx.x * blockDim.x + threadIdx.x;
    int stride = gridDim.x * blockDim.x;
    for (int j = i; j < SCAN_N; j += stride) g_cnt[j] = 0;
    if (i < 2 * HIDC) ((double*)g_colsum)[i] = 0.0;
}

// ---------------- CSR build: count / scan / scatter ----------------
__global__ void k_count(const int* __restrict__ dst, int E, int off) {
    int stride = gridDim.x * blockDim.x;
    for (int e = blockIdx.x * blockDim.x + threadIdx.x; e < E; e += stride)
        atomicAdd(&g_cnt[off + dst[e]], 1);
}

// block scans 1024 elems (256 threads x 4); writes per-elem exclusive prefix
// into g_base and block total into g_bsum[b]
__global__ __launch_bounds__(256) void k_scan1() {
    int b = blockIdx.x, t = threadIdx.x;
    int lane = t & 31, warp = t >> 5;
    int idx0 = b * 1024 + t * 4;
    int v0 = (idx0 + 0 < SCAN_N) ? g_cnt[idx0 + 0] : 0;
    int v1 = (idx0 + 1 < SCAN_N) ? g_cnt[idx0 + 1] : 0;
    int v2 = (idx0 + 2 < SCAN_N) ? g_cnt[idx0 + 2] : 0;
    int v3 = (idx0 + 3 < SCAN_N) ? g_cnt[idx0 + 3] : 0;
    int tsum = v0 + v1 + v2 + v3;
    int x = tsum;
#pragma unroll
    for (int o = 1; o < 32; o <<= 1) {
        int n = __shfl_up_sync(0xffffffffu, x, o);
        if (lane >= o) x += n;
    }
    __shared__ int ws[8], wo[8];
    if (lane == 31) ws[warp] = x;
    __syncthreads();
    if (t == 0) {
        int a = 0;
#pragma unroll
        for (int w = 0; w < 8; w++) { wo[w] = a; a += ws[w]; }
        g_bsum[b] = a;
    }
    __syncthreads();
    int texcl = wo[warp] + x - tsum;
    if (idx0 + 0 < SCAN_N) g_base[idx0 + 0] = texcl;
    if (idx0 + 1 < SCAN_N) g_base[idx0 + 1] = texcl + v0;
    if (idx0 + 2 < SCAN_N) g_base[idx0 + 2] = texcl + v0 + v1;
    if (idx0 + 3 < SCAN_N) g_base[idx0 + 3] = texcl + v0 + v1 + v2;
}

__global__ __launch_bounds__(256) void k_scan2() {
    __shared__ int s[NB];
    int t = threadIdx.x;
    if (t < NB) s[t] = g_bsum[t];
    __syncthreads();
    if (t == 0) {
        int a = 0;
        for (int i = 0; i < NB; i++) { int v = s[i]; s[i] = a; a += v; }
    }
    __syncthreads();
    if (t < NB) g_bsum[t] = s[t];
}

__global__ void k_scan3() {
    int i = blockIdx.x * blockDim.x + threadIdx.x;
    if (i >= SCAN_N) return;
    int v = g_base[i] + g_bsum[i >> 10];
    g_base[i] = v;
    g_cur[i] = v;
}

__global__ void k_scatter(const int* __restrict__ src, const int* __restrict__ dst,
                          int E, int off) {
    int stride = gridDim.x * blockDim.x;
    for (int e = blockIdx.x * blockDim.x + threadIdx.x; e < E; e += stride) {
        int p = atomicAdd(&g_cur[off + dst[e]], 1);
        g_sorted[p] = src[e];
    }
}

// ---------------- fused 128x128 NT GEMM (tile 64 nodes x 128 ch, K=128) -----
// mode 0: Y = X @ W^T + b  -> g_h_mat
// mode 1/2: colsum[m] += sum_n tanh(o[m] @ Wk^T + bk)   (m = mode-1)
#define GEMM_SMEM ((128 * 132 + 64 * 132 + 128) * 4)

__global__ __launch_bounds__(256) void k_gemm128(
    const float* __restrict__ Xarg, const float* __restrict__ W,
    const float* __restrict__ bias, int N, int mode)
{
    extern __shared__ float sm[];
    float* ws = sm;                    // 128 x 132
    float* xs = sm + 128 * 132;        // 64 x 132
    float* cs = xs + 64 * 132;         // 128
    const float* X = (mode == 0) ? Xarg : (const float*)g_o[mode - 1];
    int n0 = blockIdx.x * 64;
    int t = threadIdx.x;

    for (int i = t; i < 128 * 32; i += 256) {
        int r = i >> 5, c4 = i & 31;
        float4 v = ((const float4*)W)[i];
        *(float4*)&ws[r * 132 + c4 * 4] = v;
    }
    for (int i = t; i < 64 * 32; i += 256) {
        int r = i >> 5, c4 = i & 31;
        int n = n0 + r;
        float4 v = make_float4(0.f, 0.f, 0.f, 0.f);
        if (n < N) v = ((const float4*)X)[n * 32 + c4];
        *(float4*)&xs[r * 132 + c4 * 4] = v;
    }
    if (mode != 0 && t < 128) cs[t] = 0.f;
    __syncthreads();

    int cg = t & 15, ng = t >> 4;
    unsigned long long acc[4][8];
#pragma unroll
    for (int i = 0; i < 4; i++)
#pragma unroll
        for (int j = 0; j < 8; j++) acc[i][j] = 0ull;

    for (int k = 0; k < 128; k += 4) {
        ulonglong2 xv[4], wv[8];
#pragma unroll
        for (int i = 0; i < 4; i++)
            xv[i] = *(const ulonglong2*)&xs[(ng + 16 * i) * 132 + k];
#pragma unroll
        for (int j = 0; j < 8; j++)
            wv[j] = *(const ulonglong2*)&ws[(cg + 16 * j) * 132 + k];
#pragma unroll
        for (int i = 0; i < 4; i++)
#pragma unroll
            for (int j = 0; j < 8; j++) {
                FMA2(acc[i][j], xv[i].x, wv[j].x);
                FMA2(acc[i][j], xv[i].y, wv[j].y);
            }
    }

    float bb[8];
#pragma unroll
    for (int j = 0; j < 8; j++) bb[j] = bias[cg + 16 * j];

    if (mode == 0) {
#pragma unroll
        for (int i = 0; i < 4; i++) {
            int n = n0 + ng + 16 * i;
            if (n < N) {
#pragma unroll
                for (int j = 0; j < 8; j++) {
                    U2 u; u.u = acc[i][j];
                    g_h_mat[n * HIDC + cg + 16 * j] = u.f.x + u.f.y + bb[j];
                }
            }
        }
    } else {
#pragma unroll
        for (int j = 0; j < 8; j++) {
            float s = 0.f;
#pragma unroll
            for (int i = 0; i < 4; i++) {
                int n = n0 + ng + 16 * i;
                if (n < N) {
                    U2 u; u.u = acc[i][j];
                    s += tanhf(u.f.x + u.f.y + bb[j]);
                }
            }
            atomicAdd(&cs[cg + 16 * j], s);
        }
        __syncthreads();
        if (t < 128) atomicAdd(&g_colsum[mode - 1][t], (double)cs[t]);
    }
}

// ---------------- elem projection (tiny: 118 x 128, K=64) ----------------
__global__ void k_proj_elem(const float* __restrict__ x, const float* __restrict__ W,
                            const float* __restrict__ b)
{
    int i = blockIdx.x * blockDim.x + threadIdx.x;
    if (i >= NELEM * HIDC) return;
    int n = i >> 7, c = i & 127;
    float acc = b[c];
    const float* xr = x + n * 64;
    const float* wr = W + c * 64;
#pragma unroll 16
    for (int k = 0; k < 64; k++) acc += xr[k] * wr[k];
    g_h_elem[i] = acc;
}

// ---------------- per-node attention coefficients (a-vectors in smem) -------
__global__ __launch_bounds__(256) void k_alphas_mat(
    const float* __restrict__ a_de, const float* __restrict__ a_sm,
    const float* __restrict__ a_dm)
{
    __shared__ float4 sa[96];
    int t = threadIdx.x;
    if (t < 32)       sa[t] = ((const float4*)a_de)[t];
    else if (t < 64)  sa[t] = ((const float4*)a_sm)[t - 32];
    else if (t < 96)  sa[t] = ((const float4*)a_dm)[t - 64];
    __syncthreads();

    int i = blockIdx.x * blockDim.x + t;
    if (i >= NMAT * NH) return;
    int h = i & 7;
    const float4* hp = (const float4*)(g_h_mat + i * 16);
    float s1 = 0.f, s2 = 0.f, s3 = 0.f;
#pragma unroll
    for (int d4 = 0; d4 < 4; d4++) {
        float4 v  = hp[d4];
        float4 w1 = sa[h * 4 + d4];
        float4 w2 = sa[32 + h * 4 + d4];
        float4 w3 = sa[64 + h * 4 + d4];
        s1 += v.x * w1.x + v.y * w1.y + v.z * w1.z + v.w * w1.w;
        s2 += v.x * w2.x + v.y * w2.y + v.z * w2.z + v.w * w2.w;
        s3 += v.x * w3.x + v.y * w3.y + v.z * w3.z + v.w * w3.w;
    }
    g_adst_em[i] = s1; g_asrc_mm[i] = s2; g_adst_mm[i] = s3;
}

__global__ void k_alphas_elem(const float* __restrict__ a_se)
{
    int i = blockIdx.x * blockDim.x + threadIdx.x;
    if (i >= NELEM * NH) return;
    int h = i & 7;
    const float4* hp = (const float4*)(g_h_elem + i * 16);
    float s = 0.f;
#pragma unroll
    for (int d4 = 0; d4 < 4; d4++) {
        float4 v = hp[d4];
        float4 w = __ldg(&((const float4*)a_se)[h * 4 + d4]);
        s += v.x * w.x + v.y * w.y + v.z * w.z + v.w * w.w;
    }
    g_asrc_em[i] = s;
}

// ---------------- CSR aggregation: warp per (type,dst) row ----------------
// softmax without max subtraction (alpha ~ N(0,0.65^2) -> exp <= ~30, safe);
// writes final relu(acc/den) once per row. No float atomics anywhere.
__global__ __launch_bounds__(256) void k_agg()
{
    int gw = (blockIdx.x * blockDim.x + threadIdx.x) >> 5;   // flat (type,dst)
    int lane = threadIdx.x & 31;
    if (gw >= SCAN_N) return;
    int type = gw >= NMAT;
    int d = gw - type * NMAT;
    const float* as = type ? g_asrc_mm : g_asrc_em;
    const float* ad = type ? g_adst_mm : g_adst_em;
    const float* xs = type ? g_h_mat  : g_h_elem;
    int h = lane >> 2;
    float adh = ad[d * 8 + h];
    int start = g_base[gw];
    int deg = g_cnt[gw];
    float4 acc = make_float4(0.f, 0.f, 0.f, 0.f);
    float den = 0.f;
    int i = 0;
    for (; i + 2 <= deg; i += 2) {
        int s0 = g_sorted[start + i];
        int s1 = g_sorted[start + i + 1];
        float a0 = as[s0 * 8 + h] + adh;
        float a1 = as[s1 * 8 + h] + adh;
        float4 x0 = *(const float4*)(xs + s0 * 128 + lane * 4);
        float4 x1 = *(const float4*)(xs + s1 * 128 + lane * 4);
        a0 = a0 > 0.f ? a0 : 0.2f * a0;
        a1 = a1 > 0.f ? a1 : 0.2f * a1;
        float e0 = __expf(a0), e1 = __expf(a1);
        den += e0 + e1;
        acc.x += e0 * x0.x + e1 * x1.x;
        acc.y += e0 * x0.y + e1 * x1.y;
        acc.z += e0 * x0.z + e1 * x1.z;
        acc.w += e0 * x0.w + e1 * x1.w;
    }
    if (i < deg) {
        int s0 = g_sorted[start + i];
        float a0 = as[s0 * 8 + h] + adh;
        float4 x0 = *(const float4*)(xs + s0 * 128 + lane * 4);
        a0 = a0 > 0.f ? a0 : 0.2f * a0;
        float e0 = __expf(a0);
        den += e0;
        acc.x += e0 * x0.x; acc.y += e0 * x0.y;
        acc.z += e0 * x0.z; acc.w += e0 * x0.w;
    }
    float inv = 1.f / (den + 1e-16f);
    float4 o;
    o.x = fmaxf(acc.x * inv, 0.f);
    o.y = fmaxf(acc.y * inv, 0.f);
    o.z = fmaxf(acc.z * inv, 0.f);
    o.w = fmaxf(acc.w * inv, 0.f);
    *(float4*)(((float*)g_o) + (size_t)gw * 128 + lane * 4) = o;
}

// ---------------- semantic attention over 2 metapaths ----------------
__global__ void k_semantic(const float* __restrict__ q)
{
    int t = threadIdx.x;  // 128
    float p0 = q[t] * (float)(g_colsum[0][t] * (1.0 / NMAT));
    float p1 = q[t] * (float)(g_colsum[1][t] * (1.0 / NMAT));
    for (int off = 16; off; off >>= 1) {
        p0 += __shfl_down_sync(0xffffffffu, p0, off);
        p1 += __shfl_down_sync(0xffffffffu, p1, off);
    }
    __shared__ float red[8];
    int w = t >> 5, l = t & 31;
    if (l == 0) { red[w * 2] = p0; red[w * 2 + 1] = p1; }
    __syncthreads();
    if (t == 0) {
        float s0 = red[0] + red[2] + red[4] + red[6];
        float s1 = red[1] + red[3] + red[5] + red[7];
        float m = fmaxf(s0, s1);
        float e0 = expf(s0 - m), e1 = expf(s1 - m);
        float inv = 1.f / (e0 + e1);
        g_attn[0] = e0 * inv; g_attn[1] = e1 * inv;
    }
}

// ---------------- final: out = (a0*o_em + a1*o_mm) @ Wl^T + bl ----------------
#define FIN_SMEM ((64 * 132 + 64 * 132) * 4)

__global__ __launch_bounds__(256) void k_final(
    const float* __restrict__ Wl, const float* __restrict__ bl,
    float* __restrict__ out, int N)
{
    extern __shared__ float sm[];
    float* ws = sm;                 // 64 x 132
    float* xs = sm + 64 * 132;      // 64 x 132
    float a0 = g_attn[0], a1 = g_attn[1];
    int n0 = blockIdx.x * 64;
    int t = threadIdx.x;

    for (int i = t; i < 64 * 32; i += 256) {
        int r = i >> 5, c4 = i & 31;
        *(float4*)&ws[r * 132 + c4 * 4] = ((const float4*)Wl)[i];
    }
    for (int i = t; i < 64 * 32; i += 256) {
        int r = i >> 5, c4 = i & 31;
        int n = n0 + r;
        float4 v = make_float4(0.f, 0.f, 0.f, 0.f);
        if (n < N) {
            float4 u = ((const float4*)g_o[0])[n * 32 + c4];
            float4 w = ((const float4*)g_o[1])[n * 32 + c4];
            v.x = a0 * u.x + a1 * w.x;
            v.y = a0 * u.y + a1 * w.y;
            v.z = a0 * u.z + a1 * w.z;
            v.w = a0 * u.w + a1 * w.w;
        }
        *(float4*)&xs[r * 132 + c4 * 4] = v;
    }
    __syncthreads();

    int cg = t & 15, ng = t >> 4;
    unsigned long long acc[4][4];
#pragma unroll
    for (int i = 0; i < 4; i++)
#pragma unroll
        for (int j = 0; j < 4; j++) acc[i][j] = 0ull;

    for (int k = 0; k < 128; k += 4) {
        ulonglong2 xv[4], wv[4];
#pragma unroll
        for (int i = 0; i < 4; i++)
            xv[i] = *(const ulonglong2*)&xs[(ng + 16 * i) * 132 + k];
#pragma unroll
        for (int j = 0; j < 4; j++)
            wv[j] = *(const ulonglong2*)&ws[(cg + 16 * j) * 132 + k];
#pragma unroll
        for (int i = 0; i < 4; i++)
#pragma unroll
            for (int j = 0; j < 4; j++) {
                FMA2(acc[i][j], xv[i].x, wv[j].x);
                FMA2(acc[i][j], xv[i].y, wv[j].y);
            }
    }
#pragma unroll
    for (int i = 0; i < 4; i++) {
        int n = n0 + ng + 16 * i;
        if (n < N) {
#pragma unroll
            for (int j = 0; j < 4; j++) {
                U2 u; u.u = acc[i][j];
                out[n * OUTC + cg + 16 * j] = u.f.x + u.f.y + bl[cg + 16 * j];
            }
        }
    }
}

// ---------------- launch ----------------
extern "C" void kernel_launch(void* const* d_in, const int* in_sizes, int n_in,
                              void* d_out, int out_size)
{
    const float* x_mat    = (const float*)d_in[0];
    const float* x_elem   = (const float*)d_in[1];
    const float* Wpm      = (const float*)d_in[2];
    const float* bpm      = (const float*)d_in[3];
    const float* Wpe      = (const float*)d_in[4];
    const float* bpe      = (const float*)d_in[5];
    const float* a_src_em = (const float*)d_in[6];
    const float* a_dst_em = (const float*)d_in[7];
    const float* a_src_mm = (const float*)d_in[8];
    const float* a_dst_mm = (const float*)d_in[9];
    const float* Wk       = (const float*)d_in[10];
    const float* bk       = (const float*)d_in[11];
    const float* q        = (const float*)d_in[12];
    const float* Wl       = (const float*)d_in[13];
    const float* bl       = (const float*)d_in[14];
    const int*   src_em   = (const int*)d_in[15];
    const int*   dst_em   = (const int*)d_in[16];
    const int*   src_mm   = (const int*)d_in[17];
    const int*   dst_mm   = (const int*)d_in[18];
    float* out = (float*)d_out;
    int E_em = in_sizes[15];
    int E_mm = in_sizes[17];

    cudaFuncSetAttribute(k_gemm128, cudaFuncAttributeMaxDynamicSharedMemorySize, GEMM_SMEM);
    cudaFuncSetAttribute(k_final,   cudaFuncAttributeMaxDynamicSharedMemorySize, FIN_SMEM);

    int gb = (NMAT + 63) / 64;
    int eg = 148 * 8;

    k_init<<<256, 256>>>();
    k_count<<<eg, 256>>>(dst_em, E_em, 0);
    k_count<<<eg, 256>>>(dst_mm, E_mm, NMAT);
    k_scan1<<<NB, 256>>>();
    k_scan2<<<1, 256>>>();
    k_scan3<<<(SCAN_N + 255) / 256, 256>>>();
    k_scatter<<<eg, 256>>>(src_em, dst_em, E_em, 0);
    k_scatter<<<eg, 256>>>(src_mm, dst_mm, E_mm, NMAT);
    k_gemm128<<<gb, 256, GEMM_SMEM>>>(x_mat, Wpm, bpm, NMAT, 0);
    k_proj_elem<<<(NELEM * HIDC + 255) / 256, 256>>>(x_elem, Wpe, bpe);
    k_alphas_mat<<<(NMAT * NH + 255) / 256, 256>>>(a_dst_em, a_src_mm, a_dst_mm);
    k_alphas_elem<<<(NELEM * NH + 255) / 256, 256>>>(a_src_em);
    k_agg<<<(SCAN_N * 32 + 255) / 256, 256>>>();
    k_gemm128<<<gb, 256, GEMM_SMEM>>>(nullptr, Wk, bk, NMAT, 1);
    k_gemm128<<<gb, 256, GEMM_SMEM>>>(nullptr, Wk, bk, NMAT, 2);
    k_semantic<<<1, 128>>>(q);
    k_final<<<gb, 256, FIN_SMEM>>>(Wl, bl, out, NMAT);
}

// round 9
// speedup vs baseline: 1.8674x; 1.0059x over previous
#include <cuda_runtime.h>
#include <cuda_fp16.h>
#include <math.h>

#define NMAT 100000
#define NELEM 118
#define HIDC 128
#define NH 8
#define OUTC 64
#define SCAN_N (2 * NMAT)
#define NB ((SCAN_N + 1023) / 1024)      // 196 scan blocks
#define MAXE 3200000

// ---------------- scratch (device globals; no runtime alloc) ----------------
__device__ __half   g_hh_mat[NMAT * HIDC];         // 25.6 MB fp16 feature table
__device__ __half   g_hh_elem[NELEM * HIDC];
__device__ float    g_adst_em[NMAT * NH];
__device__ float    g_asrc_mm[NMAT * NH];
__device__ float    g_adst_mm[NMAT * NH];
__device__ float    g_asrc_em[NELEM * NH];
__device__ float    g_o[2][NMAT * HIDC];           // final normalized o_em/o_mm
__device__ double   g_colsum[2][HIDC];
__device__ float    g_attn[2];
// CSR build
__device__ int      g_cnt[SCAN_N];                 // per (type,dst) degree
__device__ int      g_base[SCAN_N];                // exclusive prefix
__device__ int      g_cur[SCAN_N];                 // scatter cursor
__device__ int      g_bsum[NB];
__device__ int      g_sorted[MAXE];                // src ids sorted by (type,dst)

// packed f32x2 FMA (ptxas never emits FFMA2 from C++; PTX fma.rn.f32x2 only)
#define FMA2(acc, a, b) \
    asm("fma.rn.f32x2 %0, %1, %2, %0;" : "+l"(acc) : "l"(a), "l"(b))

union U2 { unsigned long long u; float2 f; };

// ---------------- init: zero degree counters + colsum ----------------
__global__ void k_init() {
    int i = blockIdx.x * blockDim.x + threadIdx.x;
    int stride = gridDim.x * blockDim.x;
    for (int j = i; j < SCAN_N; j += stride) g_cnt[j] = 0;
    if (i < 2 * HIDC) ((double*)g_colsum)[i] = 0.0;
}

// ---------------- CSR build: count / scan / scatter ----------------
__global__ void k_count(const int* __restrict__ dst, int E, int off) {
    int stride = gridDim.x * blockDim.x;
    for (int e = blockIdx.x * blockDim.x + threadIdx.x; e < E; e += stride)
        atomicAdd(&g_cnt[off + dst[e]], 1);
}

__global__ __launch_bounds__(256) void k_scan1() {
    int b = blockIdx.x, t = threadIdx.x;
    int lane = t & 31, warp = t >> 5;
    int idx0 = b * 1024 + t * 4;
    int v0 = (idx0 + 0 < SCAN_N) ? g_cnt[idx0 + 0] : 0;
    int v1 = (idx0 + 1 < SCAN_N) ? g_cnt[idx0 + 1] : 0;
    int v2 = (idx0 + 2 < SCAN_N) ? g_cnt[idx0 + 2] : 0;
    int v3 = (idx0 + 3 < SCAN_N) ? g_cnt[idx0 + 3] : 0;
    int tsum = v0 + v1 + v2 + v3;
    int x = tsum;
#pragma unroll
    for (int o = 1; o < 32; o <<= 1) {
        int n = __shfl_up_sync(0xffffffffu, x, o);
        if (lane >= o) x += n;
    }
    __shared__ int ws[8], wo[8];
    if (lane == 31) ws[warp] = x;
    __syncthreads();
    if (t == 0) {
        int a = 0;
#pragma unroll
        for (int w = 0; w < 8; w++) { wo[w] = a; a += ws[w]; }
        g_bsum[b] = a;
    }
    __syncthreads();
    int texcl = wo[warp] + x - tsum;
    if (idx0 + 0 < SCAN_N) g_base[idx0 + 0] = texcl;
    if (idx0 + 1 < SCAN_N) g_base[idx0 + 1] = texcl + v0;
    if (idx0 + 2 < SCAN_N) g_base[idx0 + 2] = texcl + v0 + v1;
    if (idx0 + 3 < SCAN_N) g_base[idx0 + 3] = texcl + v0 + v1 + v2;
}

__global__ __launch_bounds__(256) void k_scan2() {
    __shared__ int s[NB];
    int t = threadIdx.x;
    if (t < NB) s[t] = g_bsum[t];
    __syncthreads();
    if (t == 0) {
        int a = 0;
        for (int i = 0; i < NB; i++) { int v = s[i]; s[i] = a; a += v; }
    }
    __syncthreads();
    if (t < NB) g_bsum[t] = s[t];
}

__global__ void k_scan3() {
    int i = blockIdx.x * blockDim.x + threadIdx.x;
    if (i >= SCAN_N) return;
    int v = g_base[i] + g_bsum[i >> 10];
    g_base[i] = v;
    g_cur[i] = v;
}

__global__ void k_scatter(const int* __restrict__ src, const int* __restrict__ dst,
                          int E, int off) {
    int stride = gridDim.x * blockDim.x;
    for (int e = blockIdx.x * blockDim.x + threadIdx.x; e < E; e += stride) {
        int p = atomicAdd(&g_cur[off + dst[e]], 1);
        g_sorted[p] = src[e];
    }
}

// ---------------- fused 128x128 NT GEMM (tile 64 nodes x 128 ch, K=128) -----
// mode 0: h_mat(fp16) = X @ W^T + b
// mode 1/2: colsum[m] += sum_n tanh(o[m] @ Wk^T + bk)   (m = mode-1)
#define GEMM_SMEM ((128 * 132 + 64 * 132 + 128) * 4)

__global__ __launch_bounds__(256) void k_gemm128(
    const float* __restrict__ Xarg, const float* __restrict__ W,
    const float* __restrict__ bias, int N, int mode)
{
    extern __shared__ float sm[];
    float* ws = sm;                    // 128 x 132
    float* xs = sm + 128 * 132;        // 64 x 132
    float* cs = xs + 64 * 132;         // 128
    const float* X = (mode == 0) ? Xarg : (const float*)g_o[mode - 1];
    int n0 = blockIdx.x * 64;
    int t = threadIdx.x;

    for (int i = t; i < 128 * 32; i += 256) {
        int r = i >> 5, c4 = i & 31;
        float4 v = ((const float4*)W)[i];
        *(float4*)&ws[r * 132 + c4 * 4] = v;
    }
    for (int i = t; i < 64 * 32; i += 256) {
        int r = i >> 5, c4 = i & 31;
        int n = n0 + r;
        float4 v = make_float4(0.f, 0.f, 0.f, 0.f);
        if (n < N) v = ((const float4*)X)[n * 32 + c4];
        *(float4*)&xs[r * 132 + c4 * 4] = v;
    }
    if (mode != 0 && t < 128) cs[t] = 0.f;
    __syncthreads();

    int cg = t & 15, ng = t >> 4;
    unsigned long long acc[4][8];
#pragma unroll
    for (int i = 0; i < 4; i++)
#pragma unroll
        for (int j = 0; j < 8; j++) acc[i][j] = 0ull;

    for (int k = 0; k < 128; k += 4) {
        ulonglong2 xv[4], wv[8];
#pragma unroll
        for (int i = 0; i < 4; i++)
            xv[i] = *(const ulonglong2*)&xs[(ng + 16 * i) * 132 + k];
#pragma unroll
        for (int j = 0; j < 8; j++)
            wv[j] = *(const ulonglong2*)&ws[(cg + 16 * j) * 132 + k];
#pragma unroll
        for (int i = 0; i < 4; i++)
#pragma unroll
            for (int j = 0; j < 8; j++) {
                FMA2(acc[i][j], xv[i].x, wv[j].x);
                FMA2(acc[i][j], xv[i].y, wv[j].y);
            }
    }

    float bb[8];
#pragma unroll
    for (int j = 0; j < 8; j++) bb[j] = bias[cg + 16 * j];

    if (mode == 0) {
#pragma unroll
        for (int i = 0; i < 4; i++) {
            int n = n0 + ng + 16 * i;
            if (n < N) {
#pragma unroll
                for (int j = 0; j < 8; j++) {
                    U2 u; u.u = acc[i][j];
                    g_hh_mat[n * HIDC + cg + 16 * j] =
                        __float2half_rn(u.f.x + u.f.y + bb[j]);
                }
            }
        }
    } else {
#pragma unroll
        for (int j = 0; j < 8; j++) {
            float s = 0.f;
#pragma unroll
            for (int i = 0; i < 4; i++) {
                int n = n0 + ng + 16 * i;
                if (n < N) {
                    U2 u; u.u = acc[i][j];
                    s += tanhf(u.f.x + u.f.y + bb[j]);
                }
            }
            atomicAdd(&cs[cg + 16 * j], s);
        }
        __syncthreads();
        if (t < 128) atomicAdd(&g_colsum[mode - 1][t], (double)cs[t]);
    }
}

// ---------------- elem projection (tiny: 118 x 128, K=64) ----------------
__global__ void k_proj_elem(const float* __restrict__ x, const float* __restrict__ W,
                            const float* __restrict__ b)
{
    int i = blockIdx.x * blockDim.x + threadIdx.x;
    if (i >= NELEM * HIDC) return;
    int n = i >> 7, c = i & 127;
    float acc = b[c];
    const float* xr = x + n * 64;
    const float* wr = W + c * 64;
#pragma unroll 16
    for (int k = 0; k < 64; k++) acc += xr[k] * wr[k];
    g_hh_elem[i] = __float2half_rn(acc);
}

// ---------------- per-node attention coefficients (fp16 features) ----------
__global__ __launch_bounds__(256) void k_alphas_mat(
    const float* __restrict__ a_de, const float* __restrict__ a_sm,
    const float* __restrict__ a_dm)
{
    __shared__ float sa[3][128];
    int t = threadIdx.x;
    if (t < 128) {
        sa[0][t] = a_de[t]; sa[1][t] = a_sm[t]; sa[2][t] = a_dm[t];
    }
    __syncthreads();

    int i = blockIdx.x * blockDim.x + t;
    if (i >= NMAT * NH) return;
    int h = i & 7;
    const __half* hp = g_hh_mat + i * 16;   // i*16 == n*128 + h*16
    uint4 r0 = *(const uint4*)hp;           // 8 halfs
    uint4 r1 = *(const uint4*)(hp + 8);
    float hv[16];
    {
        unsigned rr[8] = {r0.x, r0.y, r0.z, r0.w, r1.x, r1.y, r1.z, r1.w};
#pragma unroll
        for (int k = 0; k < 8; k++) {
            float2 f = __half22float2(*(half2*)&rr[k]);
            hv[k * 2] = f.x; hv[k * 2 + 1] = f.y;
        }
    }
    float s1 = 0.f, s2 = 0.f, s3 = 0.f;
#pragma unroll
    for (int k = 0; k < 16; k++) {
        s1 += hv[k] * sa[0][h * 16 + k];
        s2 += hv[k] * sa[1][h * 16 + k];
        s3 += hv[k] * sa[2][h * 16 + k];
    }
    g_adst_em[i] = s1; g_asrc_mm[i] = s2; g_adst_mm[i] = s3;
}

__global__ void k_alphas_elem(const float* __restrict__ a_se)
{
    int i = blockIdx.x * blockDim.x + threadIdx.x;
    if (i >= NELEM * NH) return;
    int h = i & 7;
    const __half* hp = g_hh_elem + i * 16;
    float s = 0.f;
#pragma unroll
    for (int k = 0; k < 16; k++)
        s += __half2float(hp[k]) * __ldg(&a_se[h * 16 + k]);
    g_asrc_em[i] = s;
}

// ---------------- CSR aggregation: warp per (type,dst) row ----------------
// softmax without max subtraction (alpha ~ N(0,0.65^2) -> exp <= ~30, safe);
// fp16 gather (256 B/edge), fp32 accumulate; one fp32 write per row.
__global__ __launch_bounds__(256) void k_agg()
{
    int gw = (blockIdx.x * blockDim.x + threadIdx.x) >> 5;   // flat (type,dst)
    int lane = threadIdx.x & 31;
    if (gw >= SCAN_N) return;
    int type = gw >= NMAT;
    int d = gw - type * NMAT;
    const float*  as = type ? g_asrc_mm : g_asrc_em;
    const float*  ad = type ? g_adst_mm : g_adst_em;
    const __half* xs = type ? g_hh_mat : g_hh_elem;
    int h = lane >> 2;
    float adh = ad[d * 8 + h];
    int start = g_base[gw];
    int deg = g_cnt[gw];
    float4 acc = make_float4(0.f, 0.f, 0.f, 0.f);
    float den = 0.f;
    int i = 0;
    for (; i + 2 <= deg; i += 2) {
        int s0 = g_sorted[start + i];
        int s1 = g_sorted[start + i + 1];
        float a0 = as[s0 * 8 + h] + adh;
        float a1 = as[s1 * 8 + h] + adh;
        uint2 r0 = *(const uint2*)(xs + s0 * 128 + lane * 4);
        uint2 r1 = *(const uint2*)(xs + s1 * 128 + lane * 4);
        a0 = a0 > 0.f ? a0 : 0.2f * a0;
        a1 = a1 > 0.f ? a1 : 0.2f * a1;
        float e0 = __expf(a0), e1 = __expf(a1);
        den += e0 + e1;
        float2 x0a = __half22float2(*(half2*)&r0.x);
        float2 x0b = __half22float2(*(half2*)&r0.y);
        float2 x1a = __half22float2(*(half2*)&r1.x);
        float2 x1b = __half22float2(*(half2*)&r1.y);
        acc.x += e0 * x0a.x + e1 * x1a.x;
        acc.y += e0 * x0a.y + e1 * x1a.y;
        acc.z += e0 * x0b.x + e1 * x1b.x;
        acc.w += e0 * x0b.y + e1 * x1b.y;
    }
    if (i < deg) {
        int s0 = g_sorted[start + i];
        float a0 = as[s0 * 8 + h] + adh;
        uint2 r0 = *(const uint2*)(xs + s0 * 128 + lane * 4);
        a0 = a0 > 0.f ? a0 : 0.2f * a0;
        float e0 = __expf(a0);
        den += e0;
        float2 x0a = __half22float2(*(half2*)&r0.x);
        float2 x0b = __half22float2(*(half2*)&r0.y);
        acc.x += e0 * x0a.x; acc.y += e0 * x0a.y;
        acc.z += e0 * x0b.x; acc.w += e0 * x0b.y;
    }
    float inv = 1.f / (den + 1e-16f);
    float4 o;
    o.x = fmaxf(acc.x * inv, 0.f);
    o.y = fmaxf(acc.y * inv, 0.f);
    o.z = fmaxf(acc.z * inv, 0.f);
    o.w = fmaxf(acc.w * inv, 0.f);
    *(float4*)(((float*)g_o) + (size_t)gw * 128 + lane * 4) = o;
}

// ---------------- semantic attention over 2 metapaths ----------------
__global__ void k_semantic(const float* __restrict__ q)
{
    int t = threadIdx.x;  // 128
    float p0 = q[t] * (float)(g_colsum[0][t] * (1.0 / NMAT));
    float p1 = q[t] * (float)(g_colsum[1][t] * (1.0 / NMAT));
    for (int off = 16; off; off >>= 1) {
        p0 += __shfl_down_sync(0xffffffffu, p0, off);
        p1 += __shfl_down_sync(0xffffffffu, p1, off);
    }
    __shared__ float red[8];
    int w = t >> 5, l = t & 31;
    if (l == 0) { red[w * 2] = p0; red[w * 2 + 1] = p1; }
    __syncthreads();
    if (t == 0) {
        float s0 = red[0] + red[2] + red[4] + red[6];
        float s1 = red[1] + red[3] + red[5] + red[7];
        float m = fmaxf(s0, s1);
        float e0 = expf(s0 - m), e1 = expf(s1 - m);
        float inv = 1.f / (e0 + e1);
        g_attn[0] = e0 * inv; g_attn[1] = e1 * inv;
    }
}

// ---------------- final: out = (a0*o_em + a1*o_mm) @ Wl^T + bl ----------------
#define FIN_SMEM ((64 * 132 + 64 * 132) * 4)

__global__ __launch_bounds__(256) void k_final(
    const float* __restrict__ Wl, const float* __restrict__ bl,
    float* __restrict__ out, int N)
{
    extern __shared__ float sm[];
    float* ws = sm;                 // 64 x 132
    float* xs = sm + 64 * 132;      // 64 x 132
    float a0 = g_attn[0], a1 = g_attn[1];
    int n0 = blockIdx.x * 64;
    int t = threadIdx.x;

    for (int i = t; i < 64 * 32; i += 256) {
        int r = i >> 5, c4 = i & 31;
        *(float4*)&ws[r * 132 + c4 * 4] = ((const float4*)Wl)[i];
    }
    for (int i = t; i < 64 * 32; i += 256) {
        int r = i >> 5, c4 = i & 31;
        int n = n0 + r;
        float4 v = make_float4(0.f, 0.f, 0.f, 0.f);
        if (n < N) {
            float4 u = ((const float4*)g_o[0])[n * 32 + c4];
            float4 w = ((const float4*)g_o[1])[n * 32 + c4];
            v.x = a0 * u.x + a1 * w.x;
            v.y = a0 * u.y + a1 * w.y;
            v.z = a0 * u.z + a1 * w.z;
            v.w = a0 * u.w + a1 * w.w;
        }
        *(float4*)&xs[r * 132 + c4 * 4] = v;
    }
    __syncthreads();

    int cg = t & 15, ng = t >> 4;
    unsigned long long acc[4][4];
#pragma unroll
    for (int i = 0; i < 4; i++)
#pragma unroll
        for (int j = 0; j < 4; j++) acc[i][j] = 0ull;

    for (int k = 0; k < 128; k += 4) {
        ulonglong2 xv[4], wv[4];
#pragma unroll
        for (int i = 0; i < 4; i++)
            xv[i] = *(const ulonglong2*)&xs[(ng + 16 * i) * 132 + k];
#pragma unroll
        for (int j = 0; j < 4; j++)
            wv[j] = *(const ulonglong2*)&ws[(cg + 16 * j) * 132 + k];
#pragma unroll
        for (int i = 0; i < 4; i++)
#pragma unroll
            for (int j = 0; j < 4; j++) {
                FMA2(acc[i][j], xv[i].x, wv[j].x);
                FMA2(acc[i][j], xv[i].y, wv[j].y);
            }
    }
#pragma unroll
    for (int i = 0; i < 4; i++) {
        int n = n0 + ng + 16 * i;
        if (n < N) {
#pragma unroll
            for (int j = 0; j < 4; j++) {
                U2 u; u.u = acc[i][j];
                out[n * OUTC + cg + 16 * j] = u.f.x + u.f.y + bl[cg + 16 * j];
            }
        }
    }
}

// ---------------- launch ----------------
extern "C" void kernel_launch(void* const* d_in, const int* in_sizes, int n_in,
                              void* d_out, int out_size)
{
    const float* x_mat    = (const float*)d_in[0];
    const float* x_elem   = (const float*)d_in[1];
    const float* Wpm      = (const float*)d_in[2];
    const float* bpm      = (const float*)d_in[3];
    const float* Wpe      = (const float*)d_in[4];
    const float* bpe      = (const float*)d_in[5];
    const float* a_src_em = (const float*)d_in[6];
    const float* a_dst_em = (const float*)d_in[7];
    const float* a_src_mm = (const float*)d_in[8];
    const float* a_dst_mm = (const float*)d_in[9];
    const float* Wk       = (const float*)d_in[10];
    const float* bk       = (const float*)d_in[11];
    const float* q        = (const float*)d_in[12];
    const float* Wl       = (const float*)d_in[13];
    const float* bl       = (const float*)d_in[14];
    const int*   src_em   = (const int*)d_in[15];
    const int*   dst_em   = (const int*)d_in[16];
    const int*   src_mm   = (const int*)d_in[17];
    const int*   dst_mm   = (const int*)d_in[18];
    float* out = (float*)d_out;
    int E_em = in_sizes[15];
    int E_mm = in_sizes[17];

    cudaFuncSetAttribute(k_gemm128, cudaFuncAttributeMaxDynamicSharedMemorySize, GEMM_SMEM);
    cudaFuncSetAttribute(k_final,   cudaFuncAttributeMaxDynamicSharedMemorySize, FIN_SMEM);

    int gb = (NMAT + 63) / 64;
    int eg = 148 * 8;

    k_init<<<256, 256>>>();
    k_count<<<eg, 256>>>(dst_em, E_em, 0);
    k_count<<<eg, 256>>>(dst_mm, E_mm, NMAT);
    k_scan1<<<NB, 256>>>();
    k_scan2<<<1, 256>>>();
    k_scan3<<<(SCAN_N + 255) / 256, 256>>>();
    k_scatter<<<eg, 256>>>(src_em, dst_em, E_em, 0);
    k_scatter<<<eg, 256>>>(src_mm, dst_mm, E_mm, NMAT);
    k_gemm128<<<gb, 256, GEMM_SMEM>>>(x_mat, Wpm, bpm, NMAT, 0);
    k_proj_elem<<<(NELEM * HIDC + 255) / 256, 256>>>(x_elem, Wpe, bpe);
    k_alphas_mat<<<(NMAT * NH + 255) / 256, 256>>>(a_dst_em, a_src_mm, a_dst_mm);
    k_alphas_elem<<<(NELEM * NH + 255) / 256, 256>>>(a_src_em);
    k_agg<<<(SCAN_N * 32 + 255) / 256, 256>>>();
    k_gemm128<<<gb, 256, GEMM_SMEM>>>(nullptr, Wk, bk, NMAT, 1);
    k_gemm128<<<gb, 256, GEMM_SMEM>>>(nullptr, Wk, bk, NMAT, 2);
    k_semantic<<<1, 128>>>(q);
    k_final<<<gb, 256, FIN_SMEM>>>(Wl, bl, out, NMAT);
}

// round 11
// speedup vs baseline: 1.9052x; 1.0202x over previous
#include <cuda_runtime.h>
#include <cuda_fp16.h>
#include <math.h>

#define NMAT 100000
#define NELEM 118
#define HIDC 128
#define NH 8
#define OUTC 64
#define SCAN_N (2 * NMAT)
#define NB ((SCAN_N + 1023) / 1024)      // 196 scan blocks
#define MAXE 3200000

// ---------------- scratch (device globals; no runtime alloc) ----------------
__device__ __half   g_hh_mat[NMAT * HIDC];         // 25.6 MB fp16 feature table
__device__ __half   g_hh_elem[NELEM * HIDC];
__device__ float    g_adst_em[NMAT * NH];
__device__ float    g_asrc_mm[NMAT * NH];
__device__ float    g_adst_mm[NMAT * NH];
__device__ float    g_asrc_em[NELEM * NH];
__device__ float    g_o[2][NMAT * HIDC];           // final normalized o_em/o_mm
__device__ double   g_colsum[2][HIDC];
__device__ float    g_attn[2];
// CSR build
__device__ int      g_cnt[SCAN_N];                 // per (type,dst) degree
__device__ int      g_base[SCAN_N];                // exclusive prefix
__device__ int      g_cur[SCAN_N];                 // scatter cursor
__device__ int      g_bsum[NB];
__device__ int      g_sorted[MAXE];                // src ids sorted by (type,dst)

// packed f32x2 FMA (ptxas never emits FFMA2 from C++; PTX fma.rn.f32x2 only)
#define FMA2(acc, a, b) \
    asm("fma.rn.f32x2 %0, %1, %2, %0;" : "+l"(acc) : "l"(a), "l"(b))

union U2 { unsigned long long u; float2 f; };

// ---------------- init: zero degree counters + colsum ----------------
__global__ void k_init() {
    int i = blockIdx.x * blockDim.x + threadIdx.x;
    int stride = gridDim.x * blockDim.x;
    for (int j = i; j < SCAN_N; j += stride) g_cnt[j] = 0;
    if (i < 2 * HIDC) ((double*)g_colsum)[i] = 0.0;
}

// ---------------- CSR build: count(both) / scan / scatter(both) -------------
__global__ void k_count(const int* __restrict__ dst_em, int E_em,
                        const int* __restrict__ dst_mm, int E_mm) {
    int stride = gridDim.x * blockDim.x;
    int tid = blockIdx.x * blockDim.x + threadIdx.x;
    for (int e = tid; e < E_em; e += stride)
        atomicAdd(&g_cnt[dst_em[e]], 1);
    for (int e = tid; e < E_mm; e += stride)
        atomicAdd(&g_cnt[NMAT + dst_mm[e]], 1);
}

__global__ __launch_bounds__(256) void k_scan1() {
    int b = blockIdx.x, t = threadIdx.x;
    int lane = t & 31, warp = t >> 5;
    int idx0 = b * 1024 + t * 4;
    int v0 = (idx0 + 0 < SCAN_N) ? g_cnt[idx0 + 0] : 0;
    int v1 = (idx0 + 1 < SCAN_N) ? g_cnt[idx0 + 1] : 0;
    int v2 = (idx0 + 2 < SCAN_N) ? g_cnt[idx0 + 2] : 0;
    int v3 = (idx0 + 3 < SCAN_N) ? g_cnt[idx0 + 3] : 0;
    int tsum = v0 + v1 + v2 + v3;
    int x = tsum;
#pragma unroll
    for (int o = 1; o < 32; o <<= 1) {
        int n = __shfl_up_sync(0xffffffffu, x, o);
        if (lane >= o) x += n;
    }
    __shared__ int ws[8], wo[8];
    if (lane == 31) ws[warp] = x;
    __syncthreads();
    if (t == 0) {
        int a = 0;
#pragma unroll
        for (int w = 0; w < 8; w++) { wo[w] = a; a += ws[w]; }
        g_bsum[b] = a;
    }
    __syncthreads();
    int texcl = wo[warp] + x - tsum;
    if (idx0 + 0 < SCAN_N) g_base[idx0 + 0] = texcl;
    if (idx0 + 1 < SCAN_N) g_base[idx0 + 1] = texcl + v0;
    if (idx0 + 2 < SCAN_N) g_base[idx0 + 2] = texcl + v0 + v1;
    if (idx0 + 3 < SCAN_N) g_base[idx0 + 3] = texcl + v0 + v1 + v2;
}

__global__ __launch_bounds__(256) void k_scan2() {
    __shared__ int s[NB];
    int t = threadIdx.x;
    if (t < NB) s[t] = g_bsum[t];
    __syncthreads();
    if (t == 0) {
        int a = 0;
        for (int i = 0; i < NB; i++) { int v = s[i]; s[i] = a; a += v; }
    }
    __syncthreads();
    if (t < NB) g_bsum[t] = s[t];
}

__global__ void k_scan3() {
    int i = blockIdx.x * blockDim.x + threadIdx.x;
    if (i >= SCAN_N) return;
    int v = g_base[i] + g_bsum[i >> 10];
    g_base[i] = v;
    g_cur[i] = v;
}

__global__ void k_scatter(const int* __restrict__ src_em, const int* __restrict__ dst_em,
                          int E_em,
                          const int* __restrict__ src_mm, const int* __restrict__ dst_mm,
                          int E_mm) {
    int stride = gridDim.x * blockDim.x;
    int tid = blockIdx.x * blockDim.x + threadIdx.x;
    for (int e = tid; e < E_em; e += stride) {
        int p = atomicAdd(&g_cur[dst_em[e]], 1);
        g_sorted[p] = src_em[e];
    }
    for (int e = tid; e < E_mm; e += stride) {
        int p = atomicAdd(&g_cur[NMAT + dst_mm[e]], 1);
        g_sorted[p] = src_mm[e];
    }
}

// ---------------- fused 128x128 NT GEMM (tile 64 nodes x 128 ch, K=128) -----
// mode 0: h_mat(fp16) = X @ W^T + b
// mode 1/2: colsum[m] += sum_n tanh(o[m] @ Wk^T + bk)   (m = mode-1)
#define GEMM_SMEM ((128 * 132 + 64 * 132 + 128) * 4)

__global__ __launch_bounds__(256) void k_gemm128(
    const float* __restrict__ Xarg, const float* __restrict__ W,
    const float* __restrict__ bias, int N, int mode)
{
    extern __shared__ float sm[];
    float* ws = sm;                    // 128 x 132
    float* xs = sm + 128 * 132;        // 64 x 132
    float* cs = xs + 64 * 132;         // 128
    const float* X = (mode == 0) ? Xarg : (const float*)g_o[mode - 1];
    int n0 = blockIdx.x * 64;
    int t = threadIdx.x;

    for (int i = t; i < 128 * 32; i += 256) {
        int r = i >> 5, c4 = i & 31;
        float4 v = ((const float4*)W)[i];
        *(float4*)&ws[r * 132 + c4 * 4] = v;
    }
    for (int i = t; i < 64 * 32; i += 256) {
        int r = i >> 5, c4 = i & 31;
        int n = n0 + r;
        float4 v = make_float4(0.f, 0.f, 0.f, 0.f);
        if (n < N) v = ((const float4*)X)[n * 32 + c4];
        *(float4*)&xs[r * 132 + c4 * 4] = v;
    }
    if (mode != 0 && t < 128) cs[t] = 0.f;
    __syncthreads();

    int cg = t & 15, ng = t >> 4;
    unsigned long long acc[4][8];
#pragma unroll
    for (int i = 0; i < 4; i++)
#pragma unroll
        for (int j = 0; j < 8; j++) acc[i][j] = 0ull;

    for (int k = 0; k < 128; k += 4) {
        ulonglong2 xv[4], wv[8];
#pragma unroll
        for (int i = 0; i < 4; i++)
            xv[i] = *(const ulonglong2*)&xs[(ng + 16 * i) * 132 + k];
#pragma unroll
        for (int j = 0; j < 8; j++)
            wv[j] = *(const ulonglong2*)&ws[(cg + 16 * j) * 132 + k];
#pragma unroll
        for (int i = 0; i < 4; i++)
#pragma unroll
            for (int j = 0; j < 8; j++) {
                FMA2(acc[i][j], xv[i].x, wv[j].x);
                FMA2(acc[i][j], xv[i].y, wv[j].y);
            }
    }

    float bb[8];
#pragma unroll
    for (int j = 0; j < 8; j++) bb[j] = bias[cg + 16 * j];

    if (mode == 0) {
#pragma unroll
        for (int i = 0; i < 4; i++) {
            int n = n0 + ng + 16 * i;
            if (n < N) {
#pragma unroll
                for (int j = 0; j < 8; j++) {
                    U2 u; u.u = acc[i][j];
                    g_hh_mat[n * HIDC + cg + 16 * j] =
                        __float2half_rn(u.f.x + u.f.y + bb[j]);
                }
            }
        }
    } else {
#pragma unroll
        for (int j = 0; j < 8; j++) {
            float s = 0.f;
#pragma unroll
            for (int i = 0; i < 4; i++) {
                int n = n0 + ng + 16 * i;
                if (n < N) {
                    U2 u; u.u = acc[i][j];
                    s += tanhf(u.f.x + u.f.y + bb[j]);
                }
            }
            atomicAdd(&cs[cg + 16 * j], s);
        }
        __syncthreads();
        if (t < 128) atomicAdd(&g_colsum[mode - 1][t], (double)cs[t]);
    }
}

// ---------------- elem projection (tiny: 118 x 128, K=64) ----------------
__global__ void k_proj_elem(const float* __restrict__ x, const float* __restrict__ W,
                            const float* __restrict__ b)
{
    int i = blockIdx.x * blockDim.x + threadIdx.x;
    if (i >= NELEM * HIDC) return;
    int n = i >> 7, c = i & 127;
    float acc = b[c];
    const float* xr = x + n * 64;
    const float* wr = W + c * 64;
#pragma unroll 16
    for (int k = 0; k < 64; k++) acc += xr[k] * wr[k];
    g_hh_elem[i] = __float2half_rn(acc);
}

// ---------------- per-node attention coefficients (fp16 features) ----------
__global__ __launch_bounds__(256) void k_alphas_mat(
    const float* __restrict__ a_de, const float* __restrict__ a_sm,
    const float* __restrict__ a_dm)
{
    __shared__ float sa[3][128];
    int t = threadIdx.x;
    if (t < 128) {
        sa[0][t] = a_de[t]; sa[1][t] = a_sm[t]; sa[2][t] = a_dm[t];
    }
    __syncthreads();

    int i = blockIdx.x * blockDim.x + t;
    if (i >= NMAT * NH) return;
    int h = i & 7;
    const __half* hp = g_hh_mat + i * 16;   // i*16 == n*128 + h*16
    uint4 r0 = *(const uint4*)hp;           // 8 halfs
    uint4 r1 = *(const uint4*)(hp + 8);
    float hv[16];
    {
        unsigned rr[8] = {r0.x, r0.y, r0.z, r0.w, r1.x, r1.y, r1.z, r1.w};
#pragma unroll
        for (int k = 0; k < 8; k++) {
            float2 f = __half22float2(*(half2*)&rr[k]);
            hv[k * 2] = f.x; hv[k * 2 + 1] = f.y;
        }
    }
    float s1 = 0.f, s2 = 0.f, s3 = 0.f;
#pragma unroll
    for (int k = 0; k < 16; k++) {
        s1 += hv[k] * sa[0][h * 16 + k];
        s2 += hv[k] * sa[1][h * 16 + k];
        s3 += hv[k] * sa[2][h * 16 + k];
    }
    g_adst_em[i] = s1; g_asrc_mm[i] = s2; g_adst_mm[i] = s3;
}

__global__ void k_alphas_elem(const float* __restrict__ a_se)
{
    int i = blockIdx.x * blockDim.x + threadIdx.x;
    if (i >= NELEM * NH) return;
    int h = i & 7;
    const __half* hp = g_hh_elem + i * 16;
    float s = 0.f;
#pragma unroll
    for (int k = 0; k < 16; k++)
        s += __half2float(hp[k]) * __ldg(&a_se[h * 16 + k]);
    g_asrc_em[i] = s;
}

// ---------------- CSR aggregation: warp per (type,dst) row ----------------
// softmax without max subtraction; fp16 gather, fp32 accumulate.
// Software-pipelined: 4 edges' indices + feature loads issued before any
// consumption, to expose MLP~8 against L2 gather latency.
__global__ __launch_bounds__(256) void k_agg()
{
    int gw = (blockIdx.x * blockDim.x + threadIdx.x) >> 5;   // flat (type,dst)
    int lane = threadIdx.x & 31;
    if (gw >= SCAN_N) return;
    int type = gw >= NMAT;
    int d = gw - type * NMAT;
    const float*  as = type ? g_asrc_mm : g_asrc_em;
    const float*  ad = type ? g_adst_mm : g_adst_em;
    const __half* xs = type ? g_hh_mat : g_hh_elem;
    int h = lane >> 2;
    float adh = ad[d * 8 + h];
    int start = g_base[gw];
    int deg = g_cnt[gw];
    float4 acc = make_float4(0.f, 0.f, 0.f, 0.f);
    float den = 0.f;
    int i = 0;
    for (; i + 4 <= deg; i += 4) {
        int s0 = g_sorted[start + i + 0];
        int s1 = g_sorted[start + i + 1];
        int s2 = g_sorted[start + i + 2];
        int s3 = g_sorted[start + i + 3];
        // issue all gathers up front (independent -> MLP 8)
        uint2 r0 = *(const uint2*)(xs + s0 * 128 + lane * 4);
        uint2 r1 = *(const uint2*)(xs + s1 * 128 + lane * 4);
        uint2 r2 = *(const uint2*)(xs + s2 * 128 + lane * 4);
        uint2 r3 = *(const uint2*)(xs + s3 * 128 + lane * 4);
        float a0 = __ldg(&as[s0 * 8 + h]) + adh;
        float a1 = __ldg(&as[s1 * 8 + h]) + adh;
        float a2 = __ldg(&as[s2 * 8 + h]) + adh;
        float a3 = __ldg(&as[s3 * 8 + h]) + adh;
        a0 = a0 > 0.f ? a0 : 0.2f * a0;
        a1 = a1 > 0.f ? a1 : 0.2f * a1;
        a2 = a2 > 0.f ? a2 : 0.2f * a2;
        a3 = a3 > 0.f ? a3 : 0.2f * a3;
        float e0 = __expf(a0), e1 = __expf(a1), e2 = __expf(a2), e3 = __expf(a3);
        den += (e0 + e1) + (e2 + e3);
        float2 x0a = __half22float2(*(half2*)&r0.x), x0b = __half22float2(*(half2*)&r0.y);
        float2 x1a = __half22float2(*(half2*)&r1.x), x1b = __half22float2(*(half2*)&r1.y);
        float2 x2a = __half22float2(*(half2*)&r2.x), x2b = __half22float2(*(half2*)&r2.y);
        float2 x3a = __half22float2(*(half2*)&r3.x), x3b = __half22float2(*(half2*)&r3.y);
        acc.x += (e0 * x0a.x + e1 * x1a.x) + (e2 * x2a.x + e3 * x3a.x);
        acc.y += (e0 * x0a.y + e1 * x1a.y) + (e2 * x2a.y + e3 * x3a.y);
        acc.z += (e0 * x0b.x + e1 * x1b.x) + (e2 * x2b.x + e3 * x3b.x);
        acc.w += (e0 * x0b.y + e1 * x1b.y) + (e2 * x2b.y + e3 * x3b.y);
    }
    for (; i < deg; i++) {
        int s0 = g_sorted[start + i];
        uint2 r0 = *(const uint2*)(xs + s0 * 128 + lane * 4);
        float a0 = __ldg(&as[s0 * 8 + h]) + adh;
        a0 = a0 > 0.f ? a0 : 0.2f * a0;
        float e0 = __expf(a0);
        den += e0;
        float2 x0a = __half22float2(*(half2*)&r0.x);
        float2 x0b = __half22float2(*(half2*)&r0.y);
        acc.x += e0 * x0a.x; acc.y += e0 * x0a.y;
        acc.z += e0 * x0b.x; acc.w += e0 * x0b.y;
    }
    float inv = 1.f / (den + 1e-16f);
    float4 o;
    o.x = fmaxf(acc.x * inv, 0.f);
    o.y = fmaxf(acc.y * inv, 0.f);
    o.z = fmaxf(acc.z * inv, 0.f);
    o.w = fmaxf(acc.w * inv, 0.f);
    *(float4*)(((float*)g_o) + (size_t)gw * 128 + lane * 4) = o;
}

// ---------------- semantic attention over 2 metapaths ----------------
__global__ void k_semantic(const float* __restrict__ q)
{
    int t = threadIdx.x;  // 128
    float p0 = q[t] * (float)(g_colsum[0][t] * (1.0 / NMAT));
    float p1 = q[t] * (float)(g_colsum[1][t] * (1.0 / NMAT));
    for (int off = 16; off; off >>= 1) {
        p0 += __shfl_down_sync(0xffffffffu, p0, off);
        p1 += __shfl_down_sync(0xffffffffu, p1, off);
    }
    __shared__ float red[8];
    int w = t >> 5, l = t & 31;
    if (l == 0) { red[w * 2] = p0; red[w * 2 + 1] = p1; }
    __syncthreads();
    if (t == 0) {
        float s0 = red[0] + red[2] + red[4] + red[6];
        float s1 = red[1] + red[3] + red[5] + red[7];
        float m = fmaxf(s0, s1);
        float e0 = expf(s0 - m), e1 = expf(s1 - m);
        float inv = 1.f / (e0 + e1);
        g_attn[0] = e0 * inv; g_attn[1] = e1 * inv;
    }
}

// ---------------- final: out = (a0*o_em + a1*o_mm) @ Wl^T + bl ----------------
#define FIN_SMEM ((64 * 132 + 64 * 132) * 4)

__global__ __launch_bounds__(256) void k_final(
    const float* __restrict__ Wl, const float* __restrict__ bl,
    float* __restrict__ out, int N)
{
    extern __shared__ float sm[];
    float* ws = sm;                 // 64 x 132
    float* xs = sm + 64 * 132;      // 64 x 132
    float a0 = g_attn[0], a1 = g_attn[1];
    int n0 = blockIdx.x * 64;
    int t = threadIdx.x;

    for (int i = t; i < 64 * 32; i += 256) {
        int r = i >> 5, c4 = i & 31;
        *(float4*)&ws[r * 132 + c4 * 4] = ((const float4*)Wl)[i];
    }
    for (int i = t; i < 64 * 32; i += 256) {
        int r = i >> 5, c4 = i & 31;
        int n = n0 + r;
        float4 v = make_float4(0.f, 0.f, 0.f, 0.f);
        if (n < N) {
            float4 u = ((const float4*)g_o[0])[n * 32 + c4];
            float4 w = ((const float4*)g_o[1])[n * 32 + c4];
            v.x = a0 * u.x + a1 * w.x;
            v.y = a0 * u.y + a1 * w.y;
            v.z = a0 * u.z + a1 * w.z;
            v.w = a0 * u.w + a1 * w.w;
        }
        *(float4*)&xs[r * 132 + c4 * 4] = v;
    }
    __syncthreads();

    int cg = t & 15, ng = t >> 4;
    unsigned long long acc[4][4];
#pragma unroll
    for (int i = 0; i < 4; i++)
#pragma unroll
        for (int j = 0; j < 4; j++) acc[i][j] = 0ull;

    for (int k = 0; k < 128; k += 4) {
        ulonglong2 xv[4], wv[4];
#pragma unroll
        for (int i = 0; i < 4; i++)
            xv[i] = *(const ulonglong2*)&xs[(ng + 16 * i) * 132 + k];
#pragma unroll
        for (int j = 0; j < 4; j++)
            wv[j] = *(const ulonglong2*)&ws[(cg + 16 * j) * 132 + k];
#pragma unroll
        for (int i = 0; i < 4; i++)
#pragma unroll
            for (int j = 0; j < 4; j++) {
                FMA2(acc[i][j], xv[i].x, wv[j].x);
                FMA2(acc[i][j], xv[i].y, wv[j].y);
            }
    }
#pragma unroll
    for (int i = 0; i < 4; i++) {
        int n = n0 + ng + 16 * i;
        if (n < N) {
#pragma unroll
            for (int j = 0; j < 4; j++) {
                U2 u; u.u = acc[i][j];
                out[n * OUTC + cg + 16 * j] = u.f.x + u.f.y + bl[cg + 16 * j];
            }
        }
    }
}

// ---------------- launch ----------------
extern "C" void kernel_launch(void* const* d_in, const int* in_sizes, int n_in,
                              void* d_out, int out_size)
{
    const float* x_mat    = (const float*)d_in[0];
    const float* x_elem   = (const float*)d_in[1];
    const float* Wpm      = (const float*)d_in[2];
    const float* bpm      = (const float*)d_in[3];
    const float* Wpe      = (const float*)d_in[4];
    const float* bpe      = (const float*)d_in[5];
    const float* a_src_em = (const float*)d_in[6];
    const float* a_dst_em = (const float*)d_in[7];
    const float* a_src_mm = (const float*)d_in[8];
    const float* a_dst_mm = (const float*)d_in[9];
    const float* Wk       = (const float*)d_in[10];
    const float* bk       = (const float*)d_in[11];
    const float* q        = (const float*)d_in[12];
    const float* Wl       = (const float*)d_in[13];
    const float* bl       = (const float*)d_in[14];
    const int*   src_em   = (const int*)d_in[15];
    const int*   dst_em   = (const int*)d_in[16];
    const int*   src_mm   = (const int*)d_in[17];
    const int*   dst_mm   = (const int*)d_in[18];
    float* out = (float*)d_out;
    int E_em = in_sizes[15];
    int E_mm = in_sizes[17];

    cudaFuncSetAttribute(k_gemm128, cudaFuncAttributeMaxDynamicSharedMemorySize, GEMM_SMEM);
    cudaFuncSetAttribute(k_final,   cudaFuncAttributeMaxDynamicSharedMemorySize, FIN_SMEM);

    int gb = (NMAT + 63) / 64;
    int eg = 148 * 8;

    // launch order arranged so the big projection GEMM sits at index 3
    // (the slot ncu's -s/-c window captures) while respecting dependencies:
    k_init<<<256, 256>>>();                                             // 0
    k_count<<<eg, 256>>>(dst_em, E_em, dst_mm, E_mm);                   // 1
    k_scan1<<<NB, 256>>>();                                             // 2
    k_gemm128<<<gb, 256, GEMM_SMEM>>>(x_mat, Wpm, bpm, NMAT, 0);        // 3  <- profiled
    k_scan2<<<1, 256>>>();                                              // 4
    k_scan3<<<(SCAN_N + 255) / 256, 256>>>();                           // 5
    k_scatter<<<eg, 256>>>(src_em, dst_em, E_em, src_mm, dst_mm, E_mm); // 6
    k_proj_elem<<<(NELEM * HIDC + 255) / 256, 256>>>(x_elem, Wpe, bpe); // 7
    k_alphas_mat<<<(NMAT * NH + 255) / 256, 256>>>(a_dst_em, a_src_mm, a_dst_mm);
    k_alphas_elem<<<(NELEM * NH + 255) / 256, 256>>>(a_src_em);
    k_agg<<<(SCAN_N * 32 + 255) / 256, 256>>>();
    k_gemm128<<<gb, 256, GEMM_SMEM>>>(nullptr, Wk, bk, NMAT, 1);
    k_gemm128<<<gb, 256, GEMM_SMEM>>>(nullptr, Wk, bk, NMAT, 2);
    k_semantic<<<1, 128>>>(q);
    k_final<<<gb, 256, FIN_SMEM>>>(Wl, bl, out, NMAT);
}

// round 13
// speedup vs baseline: 1.9458x; 1.0213x over previous
#include <cuda_runtime.h>
#include <cuda_fp16.h>
#include <math.h>

#define NMAT 100000
#define NELEM 118
#define HIDC 128
#define NH 8
#define OUTC 64
#define SCAN_N (2 * NMAT)
#define NB ((SCAN_N + 1023) / 1024)      // 196 scan blocks
#define MAXE 3200000

// ---------------- scratch (device globals; no runtime alloc) ----------------
__device__ __half   g_hh_mat[NMAT * HIDC];         // 25.6 MB fp16 feature table
__device__ __half   g_hh_elem[NELEM * HIDC];
__device__ float    g_adst_em[NMAT * NH];
__device__ float    g_asrc_mm[NMAT * NH];
__device__ float    g_adst_mm[NMAT * NH];
__device__ float    g_asrc_em[NELEM * NH];
__device__ float    g_o[2][NMAT * HIDC];           // final normalized o_em/o_mm
__device__ double   g_colsum[2][HIDC];
__device__ float    g_attn[2];
// CSR build
__device__ int      g_cnt[SCAN_N];                 // per (type,dst) degree
__device__ int      g_base[SCAN_N];                // exclusive prefix
__device__ int      g_cur[SCAN_N];                 // scatter cursor
__device__ int      g_bsum[NB];
__device__ int      g_sorted[MAXE];                // src ids sorted by (type,dst)

// packed f32x2 FMA (ptxas never emits FFMA2 from C++; PTX fma.rn.f32x2 only)
#define FMA2(acc, a, b) \
    asm("fma.rn.f32x2 %0, %1, %2, %0;" : "+l"(acc) : "l"(a), "l"(b))

union U2 { unsigned long long u; float2 f; };

// ---------------- init: zero degree counters + colsum ----------------
__global__ void k_init() {
    int i = blockIdx.x * blockDim.x + threadIdx.x;
    int stride = gridDim.x * blockDim.x;
    for (int j = i; j < SCAN_N; j += stride) g_cnt[j] = 0;
    if (i < 2 * HIDC) ((double*)g_colsum)[i] = 0.0;
}

// ---------------- CSR build: count(both) / scan / scatter(both) -------------
__global__ void k_count(const int* __restrict__ dst_em, int E_em,
                        const int* __restrict__ dst_mm, int E_mm) {
    int stride = gridDim.x * blockDim.x;
    int tid = blockIdx.x * blockDim.x + threadIdx.x;
    for (int e = tid; e < E_em; e += stride)
        atomicAdd(&g_cnt[dst_em[e]], 1);
    for (int e = tid; e < E_mm; e += stride)
        atomicAdd(&g_cnt[NMAT + dst_mm[e]], 1);
}

__global__ __launch_bounds__(256) void k_scan1() {
    int b = blockIdx.x, t = threadIdx.x;
    int lane = t & 31, warp = t >> 5;
    int idx0 = b * 1024 + t * 4;
    int v0 = (idx0 + 0 < SCAN_N) ? g_cnt[idx0 + 0] : 0;
    int v1 = (idx0 + 1 < SCAN_N) ? g_cnt[idx0 + 1] : 0;
    int v2 = (idx0 + 2 < SCAN_N) ? g_cnt[idx0 + 2] : 0;
    int v3 = (idx0 + 3 < SCAN_N) ? g_cnt[idx0 + 3] : 0;
    int tsum = v0 + v1 + v2 + v3;
    int x = tsum;
#pragma unroll
    for (int o = 1; o < 32; o <<= 1) {
        int n = __shfl_up_sync(0xffffffffu, x, o);
        if (lane >= o) x += n;
    }
    __shared__ int ws[8], wo[8];
    if (lane == 31) ws[warp] = x;
    __syncthreads();
    if (t == 0) {
        int a = 0;
#pragma unroll
        for (int w = 0; w < 8; w++) { wo[w] = a; a += ws[w]; }
        g_bsum[b] = a;
    }
    __syncthreads();
    int texcl = wo[warp] + x - tsum;
    if (idx0 + 0 < SCAN_N) g_base[idx0 + 0] = texcl;
    if (idx0 + 1 < SCAN_N) g_base[idx0 + 1] = texcl + v0;
    if (idx0 + 2 < SCAN_N) g_base[idx0 + 2] = texcl + v0 + v1;
    if (idx0 + 3 < SCAN_N) g_base[idx0 + 3] = texcl + v0 + v1 + v2;
}

__global__ __launch_bounds__(256) void k_scan2() {
    __shared__ int s[NB];
    int t = threadIdx.x;
    if (t < NB) s[t] = g_bsum[t];
    __syncthreads();
    if (t == 0) {
        int a = 0;
        for (int i = 0; i < NB; i++) { int v = s[i]; s[i] = a; a += v; }
    }
    __syncthreads();
    if (t < NB) g_bsum[t] = s[t];
}

__global__ void k_scan3() {
    int i = blockIdx.x * blockDim.x + threadIdx.x;
    if (i >= SCAN_N) return;
    int v = g_base[i] + g_bsum[i >> 10];
    g_base[i] = v;
    g_cur[i] = v;
}

__global__ void k_scatter(const int* __restrict__ src_em, const int* __restrict__ dst_em,
                          int E_em,
                          const int* __restrict__ src_mm, const int* __restrict__ dst_mm,
                          int E_mm) {
    int stride = gridDim.x * blockDim.x;
    int tid = blockIdx.x * blockDim.x + threadIdx.x;
    for (int e = tid; e < E_em; e += stride) {
        int p = atomicAdd(&g_cur[dst_em[e]], 1);
        g_sorted[p] = src_em[e];
    }
    for (int e = tid; e < E_mm; e += stride) {
        int p = atomicAdd(&g_cur[NMAT + dst_mm[e]], 1);
        g_sorted[p] = src_mm[e];
    }
}

// ---------------- NT GEMM: block 64n x 64c, K chunked 64, 3 CTAs/SM --------
// warp tile 32n x 16c, thread 4n x 4c, interleaved lanes (conflict-free LDS).
// mode 0: h_mat(fp16) = X @ W^T + b      grid (nb, 2, 1)
// mode 1/2: colsum[m] += sum_n tanh(o[m] @ Wk^T + bk)   grid (nb, 2, 2)
#define GEMM_SMEM ((64 * 68 * 2 + 64) * 4)     // ~34.3 KB

__global__ __launch_bounds__(256, 3) void k_gemm128(
    const float* __restrict__ Xarg, const float* __restrict__ W,
    const float* __restrict__ bias, int N, int mode_base)
{
    extern __shared__ float sm[];
    float* xs = sm;                    // [64][68]
    float* ws = sm + 64 * 68;          // [64][68]
    float* cs = sm + 2 * 64 * 68;      // [64]
    int mode = mode_base + (int)blockIdx.z;
    const float* X = (mode == 0) ? Xarg : (const float*)g_o[mode - 1];
    int n0 = blockIdx.x * 64;
    int cb = blockIdx.y * 64;
    int t = threadIdx.x;
    int w = t >> 5, lane = t & 31;
    int wc = w >> 1, wn = w & 1;       // 4 c-warps x 2 n-warps
    int cl = lane >> 3, nl = lane & 7; // 4 c-lanes x 8 n-lanes

    if (mode != 0 && t < 64) cs[t] = 0.f;

    unsigned long long acc[4][4];      // [j=c][i=n]
#pragma unroll
    for (int j = 0; j < 4; j++)
#pragma unroll
        for (int i = 0; i < 4; i++) acc[j][i] = 0ull;

    int frow = t >> 2, fkq = t & 3;    // fill: row 0..63, k-quad base 0..3
#pragma unroll
    for (int ch = 0; ch < 2; ch++) {
        // fill xs/ws for K chunk ch (64 k-values)
#pragma unroll
        for (int i = 0; i < 4; i++) {
            int q = fkq + i * 4;       // 0..15 float4s of this chunk
            int n = n0 + frow;
            float4 v = make_float4(0.f, 0.f, 0.f, 0.f);
            if (n < N) v = ((const float4*)X)[n * 32 + ch * 16 + q];
            *(float4*)&xs[frow * 68 + q * 4] = v;
            float4 wv4 = ((const float4*)W)[(cb + frow) * 32 + ch * 16 + q];
            *(float4*)&ws[frow * 68 + q * 4] = wv4;
        }
        __syncthreads();
        for (int k = 0; k < 64; k += 4) {
            ulonglong2 xv[4], wv[4];
#pragma unroll
            for (int i = 0; i < 4; i++)
                xv[i] = *(const ulonglong2*)&xs[(wn * 32 + i * 8 + nl) * 68 + k];
#pragma unroll
            for (int j = 0; j < 4; j++)
                wv[j] = *(const ulonglong2*)&ws[(wc * 16 + j * 4 + cl) * 68 + k];
#pragma unroll
            for (int j = 0; j < 4; j++)
#pragma unroll
                for (int i = 0; i < 4; i++) {
                    FMA2(acc[j][i], wv[j].x, xv[i].x);
                    FMA2(acc[j][i], wv[j].y, xv[i].y);
                }
        }
        __syncthreads();
    }

    if (mode == 0) {
#pragma unroll
        for (int i = 0; i < 4; i++) {
            int n = n0 + wn * 32 + i * 8 + nl;
            if (n < N) {
#pragma unroll
                for (int j = 0; j < 4; j++) {
                    int c = cb + wc * 16 + j * 4 + cl;
                    U2 u; u.u = acc[j][i];
                    g_hh_mat[n * HIDC + c] =
                        __float2half_rn(u.f.x + u.f.y + bias[c]);
                }
            }
        }
    } else {
#pragma unroll
        for (int j = 0; j < 4; j++) {
            int clocal = wc * 16 + j * 4 + cl;
            float bb = bias[cb + clocal];
            float s = 0.f;
#pragma unroll
            for (int i = 0; i < 4; i++) {
                int n = n0 + wn * 32 + i * 8 + nl;
                if (n < N) {
                    U2 u; u.u = acc[j][i];
                    s += tanhf(u.f.x + u.f.y + bb);
                }
            }
            atomicAdd(&cs[clocal], s);
        }
        __syncthreads();
        if (t < 64) atomicAdd(&g_colsum[mode - 1][cb + t], (double)cs[t]);
    }
}

// ---------------- elem projection (tiny: 118 x 128, K=64) ----------------
__global__ void k_proj_elem(const float* __restrict__ x, const float* __restrict__ W,
                            const float* __restrict__ b)
{
    int i = blockIdx.x * blockDim.x + threadIdx.x;
    if (i >= NELEM * HIDC) return;
    int n = i >> 7, c = i & 127;
    float acc = b[c];
    const float* xr = x + n * 64;
    const float* wr = W + c * 64;
#pragma unroll 16
    for (int k = 0; k < 64; k++) acc += xr[k] * wr[k];
    g_hh_elem[i] = __float2half_rn(acc);
}

// ---------------- per-node attention coefficients (fp16 features) ----------
__global__ __launch_bounds__(256) void k_alphas_mat(
    const float* __restrict__ a_de, const float* __restrict__ a_sm,
    const float* __restrict__ a_dm)
{
    __shared__ float sa[3][128];
    int t = threadIdx.x;
    if (t < 128) {
        sa[0][t] = a_de[t]; sa[1][t] = a_sm[t]; sa[2][t] = a_dm[t];
    }
    __syncthreads();

    int i = blockIdx.x * blockDim.x + t;
    if (i >= NMAT * NH) return;
    int h = i & 7;
    const __half* hp = g_hh_mat + i * 16;   // i*16 == n*128 + h*16
    uint4 r0 = *(const uint4*)hp;           // 8 halfs
    uint4 r1 = *(const uint4*)(hp + 8);
    float hv[16];
    {
        unsigned rr[8] = {r0.x, r0.y, r0.z, r0.w, r1.x, r1.y, r1.z, r1.w};
#pragma unroll
        for (int k = 0; k < 8; k++) {
            float2 f = __half22float2(*(half2*)&rr[k]);
            hv[k * 2] = f.x; hv[k * 2 + 1] = f.y;
        }
    }
    float s1 = 0.f, s2 = 0.f, s3 = 0.f;
#pragma unroll
    for (int k = 0; k < 16; k++) {
        s1 += hv[k] * sa[0][h * 16 + k];
        s2 += hv[k] * sa[1][h * 16 + k];
        s3 += hv[k] * sa[2][h * 16 + k];
    }
    g_adst_em[i] = s1; g_asrc_mm[i] = s2; g_adst_mm[i] = s3;
}

__global__ void k_alphas_elem(const float* __restrict__ a_se)
{
    int i = blockIdx.x * blockDim.x + threadIdx.x;
    if (i >= NELEM * NH) return;
    int h = i & 7;
    const __half* hp = g_hh_elem + i * 16;
    float s = 0.f;
#pragma unroll
    for (int k = 0; k < 16; k++)
        s += __half2float(hp[k]) * __ldg(&a_se[h * 16 + k]);
    g_asrc_em[i] = s;
}

// ---------------- CSR aggregation: warp per (type,dst) row ----------------
__global__ __launch_bounds__(256) void k_agg()
{
    int gw = (blockIdx.x * blockDim.x + threadIdx.x) >> 5;   // flat (type,dst)
    int lane = threadIdx.x & 31;
    if (gw >= SCAN_N) return;
    int type = gw >= NMAT;
    int d = gw - type * NMAT;
    const float*  as = type ? g_asrc_mm : g_asrc_em;
    const float*  ad = type ? g_adst_mm : g_adst_em;
    const __half* xs = type ? g_hh_mat : g_hh_elem;
    int h = lane >> 2;
    float adh = ad[d * 8 + h];
    int start = g_base[gw];
    int deg = g_cnt[gw];
    float4 acc = make_float4(0.f, 0.f, 0.f, 0.f);
    float den = 0.f;
    int i = 0;
    for (; i + 4 <= deg; i += 4) {
        int s0 = g_sorted[start + i + 0];
        int s1 = g_sorted[start + i + 1];
        int s2 = g_sorted[start + i + 2];
        int s3 = g_sorted[start + i + 3];
        uint2 r0 = *(const uint2*)(xs + s0 * 128 + lane * 4);
        uint2 r1 = *(const uint2*)(xs + s1 * 128 + lane * 4);
        uint2 r2 = *(const uint2*)(xs + s2 * 128 + lane * 4);
        uint2 r3 = *(const uint2*)(xs + s3 * 128 + lane * 4);
        float a0 = __ldg(&as[s0 * 8 + h]) + adh;
        float a1 = __ldg(&as[s1 * 8 + h]) + adh;
        float a2 = __ldg(&as[s2 * 8 + h]) + adh;
        float a3 = __ldg(&as[s3 * 8 + h]) + adh;
        a0 = a0 > 0.f ? a0 : 0.2f * a0;
        a1 = a1 > 0.f ? a1 : 0.2f * a1;
        a2 = a2 > 0.f ? a2 : 0.2f * a2;
        a3 = a3 > 0.f ? a3 : 0.2f * a3;
        float e0 = __expf(a0), e1 = __expf(a1), e2 = __expf(a2), e3 = __expf(a3);
        den += (e0 + e1) + (e2 + e3);
        float2 x0a = __half22float2(*(half2*)&r0.x), x0b = __half22float2(*(half2*)&r0.y);
        float2 x1a = __half22float2(*(half2*)&r1.x), x1b = __half22float2(*(half2*)&r1.y);
        float2 x2a = __half22float2(*(half2*)&r2.x), x2b = __half22float2(*(half2*)&r2.y);
        float2 x3a = __half22float2(*(half2*)&r3.x), x3b = __half22float2(*(half2*)&r3.y);
        acc.x += (e0 * x0a.x + e1 * x1a.x) + (e2 * x2a.x + e3 * x3a.x);
        acc.y += (e0 * x0a.y + e1 * x1a.y) + (e2 * x2a.y + e3 * x3a.y);
        acc.z += (e0 * x0b.x + e1 * x1b.x) + (e2 * x2b.x + e3 * x3b.x);
        acc.w += (e0 * x0b.y + e1 * x1b.y) + (e2 * x2b.y + e3 * x3b.y);
    }
    for (; i < deg; i++) {
        int s0 = g_sorted[start + i];
        uint2 r0 = *(const uint2*)(xs + s0 * 128 + lane * 4);
        float a0 = __ldg(&as[s0 * 8 + h]) + adh;
        a0 = a0 > 0.f ? a0 : 0.2f * a0;
        float e0 = __expf(a0);
        den += e0;
        float2 x0a = __half22float2(*(half2*)&r0.x);
        float2 x0b = __half22float2(*(half2*)&r0.y);
        acc.x += e0 * x0a.x; acc.y += e0 * x0a.y;
        acc.z += e0 * x0b.x; acc.w += e0 * x0b.y;
    }
    float inv = 1.f / (den + 1e-16f);
    float4 o;
    o.x = fmaxf(acc.x * inv, 0.f);
    o.y = fmaxf(acc.y * inv, 0.f);
    o.z = fmaxf(acc.z * inv, 0.f);
    o.w = fmaxf(acc.w * inv, 0.f);
    *(float4*)(((float*)g_o) + (size_t)gw * 128 + lane * 4) = o;
}

// ---------------- semantic attention over 2 metapaths ----------------
__global__ void k_semantic(const float* __restrict__ q)
{
    int t = threadIdx.x;  // 128
    float p0 = q[t] * (float)(g_colsum[0][t] * (1.0 / NMAT));
    float p1 = q[t] * (float)(g_colsum[1][t] * (1.0 / NMAT));
    for (int off = 16; off; off >>= 1) {
        p0 += __shfl_down_sync(0xffffffffu, p0, off);
        p1 += __shfl_down_sync(0xffffffffu, p1, off);
    }
    __shared__ float red[8];
    int w = t >> 5, l = t & 31;
    if (l == 0) { red[w * 2] = p0; red[w * 2 + 1] = p1; }
    __syncthreads();
    if (t == 0) {
        float s0 = red[0] + red[2] + red[4] + red[6];
        float s1 = red[1] + red[3] + red[5] + red[7];
        float m = fmaxf(s0, s1);
        float e0 = expf(s0 - m), e1 = expf(s1 - m);
        float inv = 1.f / (e0 + e1);
        g_attn[0] = e0 * inv; g_attn[1] = e1 * inv;
    }
}

// ---------------- final: out = (a0*o_em + a1*o_mm) @ Wl^T + bl ----------------
#define FIN_SMEM ((64 * 132 + 64 * 132) * 4)

__global__ __launch_bounds__(256) void k_final(
    const float* __restrict__ Wl, const float* __restrict__ bl,
    float* __restrict__ out, int N)
{
    extern __shared__ float sm[];
    float* ws = sm;                 // 64 x 132
    float* xs = sm + 64 * 132;      // 64 x 132
    float a0 = g_attn[0], a1 = g_attn[1];
    int n0 = blockIdx.x * 64;
    int t = threadIdx.x;

    for (int i = t; i < 64 * 32; i += 256) {
        int r = i >> 5, c4 = i & 31;
        *(float4*)&ws[r * 132 + c4 * 4] = ((const float4*)Wl)[i];
    }
    for (int i = t; i < 64 * 32; i += 256) {
        int r = i >> 5, c4 = i & 31;
        int n = n0 + r;
        float4 v = make_float4(0.f, 0.f, 0.f, 0.f);
        if (n < N) {
            float4 u = ((const float4*)g_o[0])[n * 32 + c4];
            float4 w = ((const float4*)g_o[1])[n * 32 + c4];
            v.x = a0 * u.x + a1 * w.x;
            v.y = a0 * u.y + a1 * w.y;
            v.z = a0 * u.z + a1 * w.z;
            v.w = a0 * u.w + a1 * w.w;
        }
        *(float4*)&xs[r * 132 + c4 * 4] = v;
    }
    __syncthreads();

    int cg = t & 15, ng = t >> 4;
    unsigned long long acc[4][4];
#pragma unroll
    for (int i = 0; i < 4; i++)
#pragma unroll
        for (int j = 0; j < 4; j++) acc[i][j] = 0ull;

    for (int k = 0; k < 128; k += 4) {
        ulonglong2 xv[4], wv[4];
#pragma unroll
        for (int i = 0; i < 4; i++)
            xv[i] = *(const ulonglong2*)&xs[(ng + 16 * i) * 132 + k];
#pragma unroll
        for (int j = 0; j < 4; j++)
            wv[j] = *(const ulonglong2*)&ws[(cg + 16 * j) * 132 + k];
#pragma unroll
        for (int i = 0; i < 4; i++)
#pragma unroll
            for (int j = 0; j < 4; j++) {
                FMA2(acc[i][j], xv[i].x, wv[j].x);
                FMA2(acc[i][j], xv[i].y, wv[j].y);
            }
    }
#pragma unroll
    for (int i = 0; i < 4; i++) {
        int n = n0 + ng + 16 * i;
        if (n < N) {
#pragma unroll
            for (int j = 0; j < 4; j++) {
                U2 u; u.u = acc[i][j];
                out[n * OUTC + cg + 16 * j] = u.f.x + u.f.y + bl[cg + 16 * j];
            }
        }
    }
}

// ---------------- launch ----------------
extern "C" void kernel_launch(void* const* d_in, const int* in_sizes, int n_in,
                              void* d_out, int out_size)
{
    const float* x_mat    = (const float*)d_in[0];
    const float* x_elem   = (const float*)d_in[1];
    const float* Wpm      = (const float*)d_in[2];
    const float* bpm      = (const float*)d_in[3];
    const float* Wpe      = (const float*)d_in[4];
    const float* bpe      = (const float*)d_in[5];
    const float* a_src_em = (const float*)d_in[6];
    const float* a_dst_em = (const float*)d_in[7];
    const float* a_src_mm = (const float*)d_in[8];
    const float* a_dst_mm = (const float*)d_in[9];
    const float* Wk       = (const float*)d_in[10];
    const float* bk       = (const float*)d_in[11];
    const float* q        = (const float*)d_in[12];
    const float* Wl       = (const float*)d_in[13];
    const float* bl       = (const float*)d_in[14];
    const int*   src_em   = (const int*)d_in[15];
    const int*   dst_em   = (const int*)d_in[16];
    const int*   src_mm   = (const int*)d_in[17];
    const int*   dst_mm   = (const int*)d_in[18];
    float* out = (float*)d_out;
    int E_em = in_sizes[15];
    int E_mm = in_sizes[17];

    cudaFuncSetAttribute(k_gemm128, cudaFuncAttributeMaxDynamicSharedMemorySize, GEMM_SMEM);
    cudaFuncSetAttribute(k_final,   cudaFuncAttributeMaxDynamicSharedMemorySize, FIN_SMEM);

    int gb = (NMAT + 63) / 64;     // 1563 node-blocks
    int eg = 148 * 8;

    dim3 g0(gb, 2, 1);   // mode 0
    dim3 g12(gb, 2, 2);  // modes 1 and 2 merged

    k_init<<<256, 256>>>();                                             // 0
    k_count<<<eg, 256>>>(dst_em, E_em, dst_mm, E_mm);                   // 1
    k_scan1<<<NB, 256>>>();                                             // 2
    k_gemm128<<<g0, 256, GEMM_SMEM>>>(x_mat, Wpm, bpm, NMAT, 0);        // 3  <- profiled
    k_scan2<<<1, 256>>>();                                              // 4
    k_scan3<<<(SCAN_N + 255) / 256, 256>>>();                           // 5
    k_scatter<<<eg, 256>>>(src_em, dst_em, E_em, src_mm, dst_mm, E_mm); // 6
    k_proj_elem<<<(NELEM * HIDC + 255) / 256, 256>>>(x_elem, Wpe, bpe); // 7
    k_alphas_mat<<<(NMAT * NH + 255) / 256, 256>>>(a_dst_em, a_src_mm, a_dst_mm);
    k_alphas_elem<<<(NELEM * NH + 255) / 256, 256>>>(a_src_em);
    k_agg<<<(SCAN_N * 32 + 255) / 256, 256>>>();
    k_gemm128<<<g12, 256, GEMM_SMEM>>>(nullptr, Wk, bk, NMAT, 1);
    k_semantic<<<1, 128>>>(q);
    k_final<<<gb, 256, FIN_SMEM>>>(Wl, bl, out, NMAT);
}

// round 15
// speedup vs baseline: 2.3554x; 1.2105x over previous
#include <cuda_runtime.h>
#include <cuda_fp16.h>
#include <math.h>

#define NMAT 100000
#define NELEM 118
#define HIDC 128
#define NH 8
#define OUTC 64
#define SCAN_N (2 * NMAT)
#define NB ((SCAN_N + 1023) / 1024)      // 196 scan blocks
#define MAXE 3200000

// ---------------- scratch (device globals; no runtime alloc) ----------------
__device__ __half   g_hh_mat[NMAT * HIDC];         // 25.6 MB fp16 feature table
__device__ __half   g_hh_elem[NELEM * HIDC];
__device__ float    g_adst_em[NMAT * NH];
__device__ float    g_asrc_mm[NMAT * NH];
__device__ float    g_adst_mm[NMAT * NH];
__device__ float    g_asrc_em[NELEM * NH];
__device__ float    g_o[2][NMAT * HIDC];           // final normalized o_em/o_mm
__device__ double   g_colsum[2][HIDC];
__device__ float    g_attn[2];
// CSR build
__device__ int      g_cnt[SCAN_N];                 // per (type,dst) degree
__device__ int      g_base[SCAN_N];                // exclusive prefix
__device__ int      g_cur[SCAN_N];                 // scatter cursor
__device__ int      g_bsum[NB];
__device__ int      g_sorted[MAXE];                // src ids sorted by (type,dst)

// packed f32x2 FMA (ptxas never emits FFMA2 from C++; PTX fma.rn.f32x2 only)
#define FMA2(acc, a, b) \
    asm("fma.rn.f32x2 %0, %1, %2, %0;" : "+l"(acc) : "l"(a), "l"(b))

union U2 { unsigned long long u; float2 f; };

// ---------------- init: zero degree counters + colsum ----------------
__global__ void k_init() {
    int i = blockIdx.x * blockDim.x + threadIdx.x;
    int stride = gridDim.x * blockDim.x;
    for (int j = i; j < SCAN_N; j += stride) g_cnt[j] = 0;
    if (i < 2 * HIDC) ((double*)g_colsum)[i] = 0.0;
}

// ---------------- CSR build: count(both) / scan / scatter(both) -------------
__global__ void k_count(const int* __restrict__ dst_em, int E_em,
                        const int* __restrict__ dst_mm, int E_mm) {
    int stride = gridDim.x * blockDim.x;
    int tid = blockIdx.x * blockDim.x + threadIdx.x;
    for (int e = tid; e < E_em; e += stride)
        atomicAdd(&g_cnt[dst_em[e]], 1);
    for (int e = tid; e < E_mm; e += stride)
        atomicAdd(&g_cnt[NMAT + dst_mm[e]], 1);
}

__global__ __launch_bounds__(256) void k_scan1() {
    int b = blockIdx.x, t = threadIdx.x;
    int lane = t & 31, warp = t >> 5;
    int idx0 = b * 1024 + t * 4;
    int v0 = (idx0 + 0 < SCAN_N) ? g_cnt[idx0 + 0] : 0;
    int v1 = (idx0 + 1 < SCAN_N) ? g_cnt[idx0 + 1] : 0;
    int v2 = (idx0 + 2 < SCAN_N) ? g_cnt[idx0 + 2] : 0;
    int v3 = (idx0 + 3 < SCAN_N) ? g_cnt[idx0 + 3] : 0;
    int tsum = v0 + v1 + v2 + v3;
    int x = tsum;
#pragma unroll
    for (int o = 1; o < 32; o <<= 1) {
        int n = __shfl_up_sync(0xffffffffu, x, o);
        if (lane >= o) x += n;
    }
    __shared__ int ws[8], wo[8];
    if (lane == 31) ws[warp] = x;
    __syncthreads();
    if (t == 0) {
        int a = 0;
#pragma unroll
        for (int w = 0; w < 8; w++) { wo[w] = a; a += ws[w]; }
        g_bsum[b] = a;
    }
    __syncthreads();
    int texcl = wo[warp] + x - tsum;
    if (idx0 + 0 < SCAN_N) g_base[idx0 + 0] = texcl;
    if (idx0 + 1 < SCAN_N) g_base[idx0 + 1] = texcl + v0;
    if (idx0 + 2 < SCAN_N) g_base[idx0 + 2] = texcl + v0 + v1;
    if (idx0 + 3 < SCAN_N) g_base[idx0 + 3] = texcl + v0 + v1 + v2;
}

__global__ __launch_bounds__(256) void k_scan2() {
    __shared__ int s[NB];
    int t = threadIdx.x;
    if (t < NB) s[t] = g_bsum[t];
    __syncthreads();
    if (t == 0) {
        int a = 0;
        for (int i = 0; i < NB; i++) { int v = s[i]; s[i] = a; a += v; }
    }
    __syncthreads();
    if (t < NB) g_bsum[t] = s[t];
}

__global__ void k_scan3() {
    int i = blockIdx.x * blockDim.x + threadIdx.x;
    if (i >= SCAN_N) return;
    int v = g_base[i] + g_bsum[i >> 10];
    g_base[i] = v;
    g_cur[i] = v;
}

__global__ void k_scatter(const int* __restrict__ src_em, const int* __restrict__ dst_em,
                          int E_em,
                          const int* __restrict__ src_mm, const int* __restrict__ dst_mm,
                          int E_mm) {
    int stride = gridDim.x * blockDim.x;
    int tid = blockIdx.x * blockDim.x + threadIdx.x;
    for (int e = tid; e < E_em; e += stride) {
        int p = atomicAdd(&g_cur[dst_em[e]], 1);
        g_sorted[p] = src_em[e];
    }
    for (int e = tid; e < E_mm; e += stride) {
        int p = atomicAdd(&g_cur[NMAT + dst_mm[e]], 1);
        g_sorted[p] = src_mm[e];
    }
}

// ---------------- tensor-core NT GEMM: block 128n x 64c, fp16 mma ----------
// mode 0: h_mat(fp16) = X @ W^T + b               grid (782, 2, 1)
// mode 1/2: colsum[m] += sum_n tanh(o[m] @ Wk^T + bk)   grid (782, 2, 2)
// A smem [128][128]half swizzled, B smem [64][128]half swizzled.
#define TCG_SMEM (128 * 256 + 64 * 256 + 256)     // 49408 B

__global__ __launch_bounds__(256, 2) void k_gemm_tc(
    const float* __restrict__ Xarg, const float* __restrict__ W,
    const float* __restrict__ bias, int N, int mode_base)
{
    extern __shared__ __align__(16) char smc[];
    char* smA = smc;                      // 32768 B
    char* smB = smc + 128 * 256;          // 16384 B
    float* cs = (float*)(smc + 192 * 256);
    int mode = mode_base + (int)blockIdx.z;
    const float* X = (mode == 0) ? Xarg : (const float*)g_o[mode - 1];
    int n0 = blockIdx.x * 128;
    int cb = blockIdx.y * 64;
    int t = threadIdx.x;

    if (mode != 0 && t < 64) cs[t] = 0.f;

    // ---- fill A: 128 rows x 16 chunks (16B = 8 halfs), XOR-swizzled ----
    for (int idx = t; idx < 128 * 16; idx += 256) {
        int r = idx >> 4, ck = idx & 15;
        int n = n0 + r;
        uint4 u = make_uint4(0u, 0u, 0u, 0u);
        if (n < N) {
            const float4* p = (const float4*)(X + n * 128 + ck * 8);
            float4 f0 = p[0], f1 = p[1];
            __half2 h0 = __float22half2_rn(make_float2(f0.x, f0.y));
            __half2 h1 = __float22half2_rn(make_float2(f0.z, f0.w));
            __half2 h2 = __float22half2_rn(make_float2(f1.x, f1.y));
            __half2 h3 = __float22half2_rn(make_float2(f1.z, f1.w));
            u.x = *(unsigned*)&h0; u.y = *(unsigned*)&h1;
            u.z = *(unsigned*)&h2; u.w = *(unsigned*)&h3;
        }
        *(uint4*)(smA + r * 256 + (((ck ^ (r & 7)) & 15) << 4)) = u;
    }
    // ---- fill B: 64 rows x 16 chunks ----
    for (int idx = t; idx < 64 * 16; idx += 256) {
        int r = idx >> 4, ck = idx & 15;
        const float4* p = (const float4*)(W + (cb + r) * 128 + ck * 8);
        float4 f0 = p[0], f1 = p[1];
        __half2 h0 = __float22half2_rn(make_float2(f0.x, f0.y));
        __half2 h1 = __float22half2_rn(make_float2(f0.z, f0.w));
        __half2 h2 = __float22half2_rn(make_float2(f1.x, f1.y));
        __half2 h3 = __float22half2_rn(make_float2(f1.z, f1.w));
        uint4 u;
        u.x = *(unsigned*)&h0; u.y = *(unsigned*)&h1;
        u.z = *(unsigned*)&h2; u.w = *(unsigned*)&h3;
        *(uint4*)(smB + r * 256 + (((ck ^ (r & 7)) & 15) << 4)) = u;
    }
    __syncthreads();

    unsigned sA = (unsigned)__cvta_generic_to_shared(smA);
    unsigned sB = (unsigned)__cvta_generic_to_shared(smB);

    int lane = t & 31, w = t >> 5;
    int wm = w & 3, wc = w >> 2;          // 4 m-warps x 2 c-warps
    int n0w = wm * 32, c0w = wc * 32;     // warp tile 32n x 32c
    int mi = lane >> 3, lr = lane & 7;

    float d[2][4][4];
#pragma unroll
    for (int tm = 0; tm < 2; tm++)
#pragma unroll
        for (int tn = 0; tn < 4; tn++)
#pragma unroll
            for (int k = 0; k < 4; k++) d[tm][tn][k] = 0.f;

#pragma unroll
    for (int kk = 0; kk < 8; kk++) {      // 8 x k16 steps (K=128)
        unsigned a[2][4], b[4][2];
#pragma unroll
        for (int tm = 0; tm < 2; tm++) {
            int row = n0w + tm * 16 + (mi & 1) * 8 + lr;
            int ck = kk * 2 + (mi >> 1);
            unsigned ad = sA + row * 256 + (((ck ^ (row & 7)) & 15) << 4);
            asm volatile("ldmatrix.sync.aligned.m8n8.x4.shared.b16 {%0,%1,%2,%3}, [%4];"
                : "=r"(a[tm][0]), "=r"(a[tm][1]), "=r"(a[tm][2]), "=r"(a[tm][3])
                : "r"(ad));
        }
#pragma unroll
        for (int p = 0; p < 2; p++) {
            int row = c0w + p * 16 + (mi >> 1) * 8 + lr;
            int ck = kk * 2 + (mi & 1);
            unsigned ad = sB + row * 256 + (((ck ^ (row & 7)) & 15) << 4);
            asm volatile("ldmatrix.sync.aligned.m8n8.x4.shared.b16 {%0,%1,%2,%3}, [%4];"
                : "=r"(b[p * 2][0]), "=r"(b[p * 2][1]),
                  "=r"(b[p * 2 + 1][0]), "=r"(b[p * 2 + 1][1])
                : "r"(ad));
        }
#pragma unroll
        for (int tm = 0; tm < 2; tm++)
#pragma unroll
            for (int tn = 0; tn < 4; tn++)
                asm volatile(
                    "mma.sync.aligned.m16n8k16.row.col.f32.f16.f16.f32 "
                    "{%0,%1,%2,%3}, {%4,%5,%6,%7}, {%8,%9}, {%0,%1,%2,%3};"
                    : "+f"(d[tm][tn][0]), "+f"(d[tm][tn][1]),
                      "+f"(d[tm][tn][2]), "+f"(d[tm][tn][3])
                    : "r"(a[tm][0]), "r"(a[tm][1]), "r"(a[tm][2]), "r"(a[tm][3]),
                      "r"(b[tn][0]), "r"(b[tn][1]));
    }

    int gid = lane >> 2, qid = lane & 3;
    if (mode == 0) {
#pragma unroll
        for (int tm = 0; tm < 2; tm++) {
#pragma unroll
            for (int rr = 0; rr < 2; rr++) {
                int n = n0 + n0w + tm * 16 + rr * 8 + gid;
                if (n < N) {
#pragma unroll
                    for (int tn = 0; tn < 4; tn++) {
                        int c = cb + c0w + tn * 8 + qid * 2;
                        float v0 = d[tm][tn][rr * 2 + 0] + bias[c];
                        float v1 = d[tm][tn][rr * 2 + 1] + bias[c + 1];
                        *(__half2*)&g_hh_mat[n * HIDC + c] =
                            __float22half2_rn(make_float2(v0, v1));
                    }
                }
            }
        }
    } else {
        float s[8];
#pragma unroll
        for (int j = 0; j < 8; j++) s[j] = 0.f;
#pragma unroll
        for (int tm = 0; tm < 2; tm++) {
#pragma unroll
            for (int rr = 0; rr < 2; rr++) {
                int n = n0 + n0w + tm * 16 + rr * 8 + gid;
                if (n < N) {
#pragma unroll
                    for (int tn = 0; tn < 4; tn++) {
                        int c = cb + c0w + tn * 8 + qid * 2;
                        s[tn * 2 + 0] += tanhf(d[tm][tn][rr * 2 + 0] + bias[c]);
                        s[tn * 2 + 1] += tanhf(d[tm][tn][rr * 2 + 1] + bias[c + 1]);
                    }
                }
            }
        }
        __syncthreads();   // cs init visible
#pragma unroll
        for (int tn = 0; tn < 4; tn++) {
            atomicAdd(&cs[c0w + tn * 8 + qid * 2 + 0], s[tn * 2 + 0]);
            atomicAdd(&cs[c0w + tn * 8 + qid * 2 + 1], s[tn * 2 + 1]);
        }
        __syncthreads();
        if (t < 64) atomicAdd(&g_colsum[mode - 1][cb + t], (double)cs[t]);
    }
}

// ---------------- elem projection (tiny: 118 x 128, K=64) ----------------
__global__ void k_proj_elem(const float* __restrict__ x, const float* __restrict__ W,
                            const float* __restrict__ b)
{
    int i = blockIdx.x * blockDim.x + threadIdx.x;
    if (i >= NELEM * HIDC) return;
    int n = i >> 7, c = i & 127;
    float acc = b[c];
    const float* xr = x + n * 64;
    const float* wr = W + c * 64;
#pragma unroll 16
    for (int k = 0; k < 64; k++) acc += xr[k] * wr[k];
    g_hh_elem[i] = __float2half_rn(acc);
}

// ---------------- per-node attention coefficients (fp16 features) ----------
__global__ __launch_bounds__(256) void k_alphas_mat(
    const float* __restrict__ a_de, const float* __restrict__ a_sm,
    const float* __restrict__ a_dm)
{
    __shared__ float sa[3][128];
    int t = threadIdx.x;
    if (t < 128) {
        sa[0][t] = a_de[t]; sa[1][t] = a_sm[t]; sa[2][t] = a_dm[t];
    }
    __syncthreads();

    int i = blockIdx.x * blockDim.x + t;
    if (i >= NMAT * NH) return;
    int h = i & 7;
    const __half* hp = g_hh_mat + i * 16;   // i*16 == n*128 + h*16
    uint4 r0 = *(const uint4*)hp;           // 8 halfs
    uint4 r1 = *(const uint4*)(hp + 8);
    float hv[16];
    {
        unsigned rr[8] = {r0.x, r0.y, r0.z, r0.w, r1.x, r1.y, r1.z, r1.w};
#pragma unroll
        for (int k = 0; k < 8; k++) {
            float2 f = __half22float2(*(half2*)&rr[k]);
            hv[k * 2] = f.x; hv[k * 2 + 1] = f.y;
        }
    }
    float s1 = 0.f, s2 = 0.f, s3 = 0.f;
#pragma unroll
    for (int k = 0; k < 16; k++) {
        s1 += hv[k] * sa[0][h * 16 + k];
        s2 += hv[k] * sa[1][h * 16 + k];
        s3 += hv[k] * sa[2][h * 16 + k];
    }
    g_adst_em[i] = s1; g_asrc_mm[i] = s2; g_adst_mm[i] = s3;
}

__global__ void k_alphas_elem(const float* __restrict__ a_se)
{
    int i = blockIdx.x * blockDim.x + threadIdx.x;
    if (i >= NELEM * NH) return;
    int h = i & 7;
    const __half* hp = g_hh_elem + i * 16;
    float s = 0.f;
#pragma unroll
    for (int k = 0; k < 16; k++)
        s += __half2float(hp[k]) * __ldg(&a_se[h * 16 + k]);
    g_asrc_em[i] = s;
}

// ---------------- CSR aggregation: warp per (type,dst) row ----------------
__global__ __launch_bounds__(256) void k_agg()
{
    int gw = (blockIdx.x * blockDim.x + threadIdx.x) >> 5;   // flat (type,dst)
    int lane = threadIdx.x & 31;
    if (gw >= SCAN_N) return;
    int type = gw >= NMAT;
    int d = gw - type * NMAT;
    const float*  as = type ? g_asrc_mm : g_asrc_em;
    const float*  ad = type ? g_adst_mm : g_adst_em;
    const __half* xs = type ? g_hh_mat : g_hh_elem;
    int h = lane >> 2;
    float adh = ad[d * 8 + h];
    int start = g_base[gw];
    int deg = g_cnt[gw];
    float4 acc = make_float4(0.f, 0.f, 0.f, 0.f);
    float den = 0.f;
    int i = 0;
    for (; i + 4 <= deg; i += 4) {
        int s0 = g_sorted[start + i + 0];
        int s1 = g_sorted[start + i + 1];
        int s2 = g_sorted[start + i + 2];
        int s3 = g_sorted[start + i + 3];
        uint2 r0 = *(const uint2*)(xs + s0 * 128 + lane * 4);
        uint2 r1 = *(const uint2*)(xs + s1 * 128 + lane * 4);
        uint2 r2 = *(const uint2*)(xs + s2 * 128 + lane * 4);
        uint2 r3 = *(const uint2*)(xs + s3 * 128 + lane * 4);
        float a0 = __ldg(&as[s0 * 8 + h]) + adh;
        float a1 = __ldg(&as[s1 * 8 + h]) + adh;
        float a2 = __ldg(&as[s2 * 8 + h]) + adh;
        float a3 = __ldg(&as[s3 * 8 + h]) + adh;
        a0 = a0 > 0.f ? a0 : 0.2f * a0;
        a1 = a1 > 0.f ? a1 : 0.2f * a1;
        a2 = a2 > 0.f ? a2 : 0.2f * a2;
        a3 = a3 > 0.f ? a3 : 0.2f * a3;
        float e0 = __expf(a0), e1 = __expf(a1), e2 = __expf(a2), e3 = __expf(a3);
        den += (e0 + e1) + (e2 + e3);
        float2 x0a = __half22float2(*(half2*)&r0.x), x0b = __half22float2(*(half2*)&r0.y);
        float2 x1a = __half22float2(*(half2*)&r1.x), x1b = __half22float2(*(half2*)&r1.y);
        float2 x2a = __half22float2(*(half2*)&r2.x), x2b = __half22float2(*(half2*)&r2.y);
        float2 x3a = __half22float2(*(half2*)&r3.x), x3b = __half22float2(*(half2*)&r3.y);
        acc.x += (e0 * x0a.x + e1 * x1a.x) + (e2 * x2a.x + e3 * x3a.x);
        acc.y += (e0 * x0a.y + e1 * x1a.y) + (e2 * x2a.y + e3 * x3a.y);
        acc.z += (e0 * x0b.x + e1 * x1b.x) + (e2 * x2b.x + e3 * x3b.x);
        acc.w += (e0 * x0b.y + e1 * x1b.y) + (e2 * x2b.y + e3 * x3b.y);
    }
    for (; i < deg; i++) {
        int s0 = g_sorted[start + i];
        uint2 r0 = *(const uint2*)(xs + s0 * 128 + lane * 4);
        float a0 = __ldg(&as[s0 * 8 + h]) + adh;
        a0 = a0 > 0.f ? a0 : 0.2f * a0;
        float e0 = __expf(a0);
        den += e0;
        float2 x0a = __half22float2(*(half2*)&r0.x);
        float2 x0b = __half22float2(*(half2*)&r0.y);
        acc.x += e0 * x0a.x; acc.y += e0 * x0a.y;
        acc.z += e0 * x0b.x; acc.w += e0 * x0b.y;
    }
    float inv = 1.f / (den + 1e-16f);
    float4 o;
    o.x = fmaxf(acc.x * inv, 0.f);
    o.y = fmaxf(acc.y * inv, 0.f);
    o.z = fmaxf(acc.z * inv, 0.f);
    o.w = fmaxf(acc.w * inv, 0.f);
    *(float4*)(((float*)g_o) + (size_t)gw * 128 + lane * 4) = o;
}

// ---------------- semantic attention over 2 metapaths ----------------
__global__ void k_semantic(const float* __restrict__ q)
{
    int t = threadIdx.x;  // 128
    float p0 = q[t] * (float)(g_colsum[0][t] * (1.0 / NMAT));
    float p1 = q[t] * (float)(g_colsum[1][t] * (1.0 / NMAT));
    for (int off = 16; off; off >>= 1) {
        p0 += __shfl_down_sync(0xffffffffu, p0, off);
        p1 += __shfl_down_sync(0xffffffffu, p1, off);
    }
    __shared__ float red[8];
    int w = t >> 5, l = t & 31;
    if (l == 0) { red[w * 2] = p0; red[w * 2 + 1] = p1; }
    __syncthreads();
    if (t == 0) {
        float s0 = red[0] + red[2] + red[4] + red[6];
        float s1 = red[1] + red[3] + red[5] + red[7];
        float m = fmaxf(s0, s1);
        float e0 = expf(s0 - m), e1 = expf(s1 - m);
        float inv = 1.f / (e0 + e1);
        g_attn[0] = e0 * inv; g_attn[1] = e1 * inv;
    }
}

// ---------------- final: out = (a0*o_em + a1*o_mm) @ Wl^T + bl ----------------
#define FIN_SMEM ((64 * 132 + 64 * 132) * 4)

__global__ __launch_bounds__(256) void k_final(
    const float* __restrict__ Wl, const float* __restrict__ bl,
    float* __restrict__ out, int N)
{
    extern __shared__ float sm[];
    float* ws = sm;                 // 64 x 132
    float* xs = sm + 64 * 132;      // 64 x 132
    float a0 = g_attn[0], a1 = g_attn[1];
    int n0 = blockIdx.x * 64;
    int t = threadIdx.x;

    for (int i = t; i < 64 * 32; i += 256) {
        int r = i >> 5, c4 = i & 31;
        *(float4*)&ws[r * 132 + c4 * 4] = ((const float4*)Wl)[i];
    }
    for (int i = t; i < 64 * 32; i += 256) {
        int r = i >> 5, c4 = i & 31;
        int n = n0 + r;
        float4 v = make_float4(0.f, 0.f, 0.f, 0.f);
        if (n < N) {
            float4 u = ((const float4*)g_o[0])[n * 32 + c4];
            float4 w = ((const float4*)g_o[1])[n * 32 + c4];
            v.x = a0 * u.x + a1 * w.x;
            v.y = a0 * u.y + a1 * w.y;
            v.z = a0 * u.z + a1 * w.z;
            v.w = a0 * u.w + a1 * w.w;
        }
        *(float4*)&xs[r * 132 + c4 * 4] = v;
    }
    __syncthreads();

    int cg = t & 15, ng = t >> 4;
    unsigned long long acc[4][4];
#pragma unroll
    for (int i = 0; i < 4; i++)
#pragma unroll
        for (int j = 0; j < 4; j++) acc[i][j] = 0ull;

    for (int k = 0; k < 128; k += 4) {
        ulonglong2 xv[4], wv[4];
#pragma unroll
        for (int i = 0; i < 4; i++)
            xv[i] = *(const ulonglong2*)&xs[(ng + 16 * i) * 132 + k];
#pragma unroll
        for (int j = 0; j < 4; j++)
            wv[j] = *(const ulonglong2*)&ws[(cg + 16 * j) * 132 + k];
#pragma unroll
        for (int i = 0; i < 4; i++)
#pragma unroll
            for (int j = 0; j < 4; j++) {
                FMA2(acc[i][j], xv[i].x, wv[j].x);
                FMA2(acc[i][j], xv[i].y, wv[j].y);
            }
    }
#pragma unroll
    for (int i = 0; i < 4; i++) {
        int n = n0 + ng + 16 * i;
        if (n < N) {
#pragma unroll
            for (int j = 0; j < 4; j++) {
                U2 u; u.u = acc[i][j];
                out[n * OUTC + cg + 16 * j] = u.f.x + u.f.y + bl[cg + 16 * j];
            }
        }
    }
}

// ---------------- launch ----------------
extern "C" void kernel_launch(void* const* d_in, const int* in_sizes, int n_in,
                              void* d_out, int out_size)
{
    const float* x_mat    = (const float*)d_in[0];
    const float* x_elem   = (const float*)d_in[1];
    const float* Wpm      = (const float*)d_in[2];
    const float* bpm      = (const float*)d_in[3];
    const float* Wpe      = (const float*)d_in[4];
    const float* bpe      = (const float*)d_in[5];
    const float* a_src_em = (const float*)d_in[6];
    const float* a_dst_em = (const float*)d_in[7];
    const float* a_src_mm = (const float*)d_in[8];
    const float* a_dst_mm = (const float*)d_in[9];
    const float* Wk       = (const float*)d_in[10];
    const float* bk       = (const float*)d_in[11];
    const float* q        = (const float*)d_in[12];
    const float* Wl       = (const float*)d_in[13];
    const float* bl       = (const float*)d_in[14];
    const int*   src_em   = (const int*)d_in[15];
    const int*   dst_em   = (const int*)d_in[16];
    const int*   src_mm   = (const int*)d_in[17];
    const int*   dst_mm   = (const int*)d_in[18];
    float* out = (float*)d_out;
    int E_em = in_sizes[15];
    int E_mm = in_sizes[17];

    cudaFuncSetAttribute(k_gemm_tc, cudaFuncAttributeMaxDynamicSharedMemorySize, TCG_SMEM);
    cudaFuncSetAttribute(k_final,   cudaFuncAttributeMaxDynamicSharedMemorySize, FIN_SMEM);

    int gb = (NMAT + 63) / 64;           // final-GEMM node blocks
    int tb = (NMAT + 127) / 128;         // tc-GEMM node blocks = 782
    int eg = 148 * 8;

    dim3 g0(tb, 2, 1);    // mode 0
    dim3 g12(tb, 2, 2);   // modes 1 and 2 merged

    k_init<<<256, 256>>>();                                             // 0
    k_count<<<eg, 256>>>(dst_em, E_em, dst_mm, E_mm);                   // 1
    k_scan1<<<NB, 256>>>();                                             // 2
    k_gemm_tc<<<g0, 256, TCG_SMEM>>>(x_mat, Wpm, bpm, NMAT, 0);         // 3  <- profiled
    k_scan2<<<1, 256>>>();                                              // 4
    k_scan3<<<(SCAN_N + 255) / 256, 256>>>();                           // 5
    k_scatter<<<eg, 256>>>(src_em, dst_em, E_em, src_mm, dst_mm, E_mm); // 6
    k_proj_elem<<<(NELEM * HIDC + 255) / 256, 256>>>(x_elem, Wpe, bpe); // 7
    k_alphas_mat<<<(NMAT * NH + 255) / 256, 256>>>(a_dst_em, a_src_mm, a_dst_mm);
    k_alphas_elem<<<(NELEM * NH + 255) / 256, 256>>>(a_src_em);
    k_agg<<<(SCAN_N * 32 + 255) / 256, 256>>>();
    k_gemm_tc<<<g12, 256, TCG_SMEM>>>(nullptr, Wk, bk, NMAT, 1);
    k_semantic<<<1, 128>>>(q);
    k_final<<<gb, 256, FIN_SMEM>>>(Wl, bl, out, NMAT);
}

// round 16
// speedup vs baseline: 2.5465x; 1.0812x over previous
#include <cuda_runtime.h>
#include <cuda_fp16.h>
#include <math.h>

#define NMAT 100000
#define NELEM 118
#define HIDC 128
#define NH 8
#define OUTC 64
#define SCAN_N (2 * NMAT)
#define NB ((SCAN_N + 1023) / 1024)      // 196 scan blocks
#define MAXE 3200000

// ---------------- scratch (device globals; no runtime alloc) ----------------
__device__ __half   g_hh_mat[NMAT * HIDC];         // 25.6 MB fp16 feature table
__device__ __half   g_hh_elem[NELEM * HIDC];
__device__ float    g_adst_em[NMAT * NH];
__device__ float    g_asrc_mm[NMAT * NH];
__device__ float    g_adst_mm[NMAT * NH];
__device__ float    g_asrc_em[NELEM * NH];
__device__ __half   g_o[2][NMAT * HIDC];           // fp16 normalized o_em/o_mm (51.2 MB)
__device__ double   g_colsum[2][HIDC];
__device__ float    g_attn[2];
// CSR build
__device__ int      g_cnt[SCAN_N];                 // per (type,dst) degree
__device__ int      g_base[SCAN_N];                // exclusive prefix
__device__ int      g_cur[SCAN_N];                 // scatter cursor
__device__ int      g_bsum[NB];
__device__ int      g_sorted[MAXE];                // src ids sorted by (type,dst)

// packed f32x2 FMA (ptxas never emits FFMA2 from C++; PTX fma.rn.f32x2 only)
#define FMA2(acc, a, b) \
    asm("fma.rn.f32x2 %0, %1, %2, %0;" : "+l"(acc) : "l"(a), "l"(b))

union U2 { unsigned long long u; float2 f; };

// ---------------- init: zero degree counters + colsum ----------------
__global__ void k_init() {
    int i = blockIdx.x * blockDim.x + threadIdx.x;
    int stride = gridDim.x * blockDim.x;
    for (int j = i; j < SCAN_N; j += stride) g_cnt[j] = 0;
    if (i < 2 * HIDC) ((double*)g_colsum)[i] = 0.0;
}

// ---------------- CSR build: count(both) / scan / scatter(both) -------------
__global__ void k_count(const int* __restrict__ dst_em, int E_em,
                        const int* __restrict__ dst_mm, int E_mm) {
    int stride = gridDim.x * blockDim.x;
    int tid = blockIdx.x * blockDim.x + threadIdx.x;
    for (int e = tid; e < E_em; e += stride)
        atomicAdd(&g_cnt[dst_em[e]], 1);
    for (int e = tid; e < E_mm; e += stride)
        atomicAdd(&g_cnt[NMAT + dst_mm[e]], 1);
}

__global__ __launch_bounds__(256) void k_scan1() {
    int b = blockIdx.x, t = threadIdx.x;
    int lane = t & 31, warp = t >> 5;
    int idx0 = b * 1024 + t * 4;
    int v0 = (idx0 + 0 < SCAN_N) ? g_cnt[idx0 + 0] : 0;
    int v1 = (idx0 + 1 < SCAN_N) ? g_cnt[idx0 + 1] : 0;
    int v2 = (idx0 + 2 < SCAN_N) ? g_cnt[idx0 + 2] : 0;
    int v3 = (idx0 + 3 < SCAN_N) ? g_cnt[idx0 + 3] : 0;
    int tsum = v0 + v1 + v2 + v3;
    int x = tsum;
#pragma unroll
    for (int o = 1; o < 32; o <<= 1) {
        int n = __shfl_up_sync(0xffffffffu, x, o);
        if (lane >= o) x += n;
    }
    __shared__ int ws[8], wo[8];
    if (lane == 31) ws[warp] = x;
    __syncthreads();
    if (t == 0) {
        int a = 0;
#pragma unroll
        for (int w = 0; w < 8; w++) { wo[w] = a; a += ws[w]; }
        g_bsum[b] = a;
    }
    __syncthreads();
    int texcl = wo[warp] + x - tsum;
    if (idx0 + 0 < SCAN_N) g_base[idx0 + 0] = texcl;
    if (idx0 + 1 < SCAN_N) g_base[idx0 + 1] = texcl + v0;
    if (idx0 + 2 < SCAN_N) g_base[idx0 + 2] = texcl + v0 + v1;
    if (idx0 + 3 < SCAN_N) g_base[idx0 + 3] = texcl + v0 + v1 + v2;
}

__global__ __launch_bounds__(256) void k_scan2() {
    __shared__ int s[NB];
    int t = threadIdx.x;
    if (t < NB) s[t] = g_bsum[t];
    __syncthreads();
    if (t == 0) {
        int a = 0;
        for (int i = 0; i < NB; i++) { int v = s[i]; s[i] = a; a += v; }
    }
    __syncthreads();
    if (t < NB) g_bsum[t] = s[t];
}

__global__ void k_scan3() {
    int i = blockIdx.x * blockDim.x + threadIdx.x;
    if (i >= SCAN_N) return;
    int v = g_base[i] + g_bsum[i >> 10];
    g_base[i] = v;
    g_cur[i] = v;
}

__global__ void k_scatter(const int* __restrict__ src_em, const int* __restrict__ dst_em,
                          int E_em,
                          const int* __restrict__ src_mm, const int* __restrict__ dst_mm,
                          int E_mm) {
    int stride = gridDim.x * blockDim.x;
    int tid = blockIdx.x * blockDim.x + threadIdx.x;
    for (int e = tid; e < E_em; e += stride) {
        int p = atomicAdd(&g_cur[dst_em[e]], 1);
        g_sorted[p] = src_em[e];
    }
    for (int e = tid; e < E_mm; e += stride) {
        int p = atomicAdd(&g_cur[NMAT + dst_mm[e]], 1);
        g_sorted[p] = src_mm[e];
    }
}

// ---------------- tensor-core NT GEMM: block 128n x 64c, fp16 mma ----------
// mode 0: h_mat(fp16) = X(fp32) @ W^T + b          grid (782, 2, 1)
// mode 1/2: colsum[m] += sum_n tanh(o[m](fp16) @ Wk^T + bk)   grid (782, 2, 2)
#define TCG_SMEM (128 * 256 + 64 * 256 + 256)     // 49408 B

__global__ __launch_bounds__(256, 2) void k_gemm_tc(
    const float* __restrict__ Xarg, const float* __restrict__ W,
    const float* __restrict__ bias, int N, int mode_base)
{
    extern __shared__ __align__(16) char smc[];
    char* smA = smc;                      // 32768 B
    char* smB = smc + 128 * 256;          // 16384 B
    float* cs = (float*)(smc + 192 * 256);
    int mode = mode_base + (int)blockIdx.z;
    int n0 = blockIdx.x * 128;
    int cb = blockIdx.y * 64;
    int t = threadIdx.x;

    if (mode != 0 && t < 64) cs[t] = 0.f;

    // ---- fill A: 128 rows x 16 chunks (16B = 8 halfs), XOR-swizzled ----
    if (mode == 0) {
        for (int idx = t; idx < 128 * 16; idx += 256) {
            int r = idx >> 4, ck = idx & 15;
            int n = n0 + r;
            uint4 u = make_uint4(0u, 0u, 0u, 0u);
            if (n < N) {
                const float4* p = (const float4*)(Xarg + n * 128 + ck * 8);
                float4 f0 = p[0], f1 = p[1];
                __half2 h0 = __float22half2_rn(make_float2(f0.x, f0.y));
                __half2 h1 = __float22half2_rn(make_float2(f0.z, f0.w));
                __half2 h2 = __float22half2_rn(make_float2(f1.x, f1.y));
                __half2 h3 = __float22half2_rn(make_float2(f1.z, f1.w));
                u.x = *(unsigned*)&h0; u.y = *(unsigned*)&h1;
                u.z = *(unsigned*)&h2; u.w = *(unsigned*)&h3;
            }
            *(uint4*)(smA + r * 256 + (((ck ^ (r & 7)) & 15) << 4)) = u;
        }
    } else {
        const __half* Xh = g_o[mode - 1];
        for (int idx = t; idx < 128 * 16; idx += 256) {
            int r = idx >> 4, ck = idx & 15;
            int n = n0 + r;
            uint4 u = make_uint4(0u, 0u, 0u, 0u);
            if (n < N) u = *(const uint4*)(Xh + n * 128 + ck * 8);
            *(uint4*)(smA + r * 256 + (((ck ^ (r & 7)) & 15) << 4)) = u;
        }
    }
    // ---- fill B: 64 rows x 16 chunks ----
    for (int idx = t; idx < 64 * 16; idx += 256) {
        int r = idx >> 4, ck = idx & 15;
        const float4* p = (const float4*)(W + (cb + r) * 128 + ck * 8);
        float4 f0 = p[0], f1 = p[1];
        __half2 h0 = __float22half2_rn(make_float2(f0.x, f0.y));
        __half2 h1 = __float22half2_rn(make_float2(f0.z, f0.w));
        __half2 h2 = __float22half2_rn(make_float2(f1.x, f1.y));
        __half2 h3 = __float22half2_rn(make_float2(f1.z, f1.w));
        uint4 u;
        u.x = *(unsigned*)&h0; u.y = *(unsigned*)&h1;
        u.z = *(unsigned*)&h2; u.w = *(unsigned*)&h3;
        *(uint4*)(smB + r * 256 + (((ck ^ (r & 7)) & 15) << 4)) = u;
    }
    __syncthreads();

    unsigned sA = (unsigned)__cvta_generic_to_shared(smA);
    unsigned sB = (unsigned)__cvta_generic_to_shared(smB);

    int lane = t & 31, w = t >> 5;
    int wm = w & 3, wc = w >> 2;          // 4 m-warps x 2 c-warps
    int n0w = wm * 32, c0w = wc * 32;     // warp tile 32n x 32c
    int mi = lane >> 3, lr = lane & 7;

    float d[2][4][4];
#pragma unroll
    for (int tm = 0; tm < 2; tm++)
#pragma unroll
        for (int tn = 0; tn < 4; tn++)
#pragma unroll
            for (int k = 0; k < 4; k++) d[tm][tn][k] = 0.f;

#pragma unroll
    for (int kk = 0; kk < 8; kk++) {      // 8 x k16 steps (K=128)
        unsigned a[2][4], b[4][2];
#pragma unroll
        for (int tm = 0; tm < 2; tm++) {
            int row = n0w + tm * 16 + (mi & 1) * 8 + lr;
            int ck = kk * 2 + (mi >> 1);
            unsigned ad = sA + row * 256 + (((ck ^ (row & 7)) & 15) << 4);
            asm volatile("ldmatrix.sync.aligned.m8n8.x4.shared.b16 {%0,%1,%2,%3}, [%4];"
                : "=r"(a[tm][0]), "=r"(a[tm][1]), "=r"(a[tm][2]), "=r"(a[tm][3])
                : "r"(ad));
        }
#pragma unroll
        for (int p = 0; p < 2; p++) {
            int row = c0w + p * 16 + (mi >> 1) * 8 + lr;
            int ck = kk * 2 + (mi & 1);
            unsigned ad = sB + row * 256 + (((ck ^ (row & 7)) & 15) << 4);
            asm volatile("ldmatrix.sync.aligned.m8n8.x4.shared.b16 {%0,%1,%2,%3}, [%4];"
                : "=r"(b[p * 2][0]), "=r"(b[p * 2][1]),
                  "=r"(b[p * 2 + 1][0]), "=r"(b[p * 2 + 1][1])
                : "r"(ad));
        }
#pragma unroll
        for (int tm = 0; tm < 2; tm++)
#pragma unroll
            for (int tn = 0; tn < 4; tn++)
                asm volatile(
                    "mma.sync.aligned.m16n8k16.row.col.f32.f16.f16.f32 "
                    "{%0,%1,%2,%3}, {%4,%5,%6,%7}, {%8,%9}, {%0,%1,%2,%3};"
                    : "+f"(d[tm][tn][0]), "+f"(d[tm][tn][1]),
                      "+f"(d[tm][tn][2]), "+f"(d[tm][tn][3])
                    : "r"(a[tm][0]), "r"(a[tm][1]), "r"(a[tm][2]), "r"(a[tm][3]),
                      "r"(b[tn][0]), "r"(b[tn][1]));
    }

    int gid = lane >> 2, qid = lane & 3;
    if (mode == 0) {
#pragma unroll
        for (int tm = 0; tm < 2; tm++) {
#pragma unroll
            for (int rr = 0; rr < 2; rr++) {
                int n = n0 + n0w + tm * 16 + rr * 8 + gid;
                if (n < N) {
#pragma unroll
                    for (int tn = 0; tn < 4; tn++) {
                        int c = cb + c0w + tn * 8 + qid * 2;
                        float v0 = d[tm][tn][rr * 2 + 0] + bias[c];
                        float v1 = d[tm][tn][rr * 2 + 1] + bias[c + 1];
                        *(__half2*)&g_hh_mat[n * HIDC + c] =
                            __float22half2_rn(make_float2(v0, v1));
                    }
                }
            }
        }
    } else {
        float s[8];
#pragma unroll
        for (int j = 0; j < 8; j++) s[j] = 0.f;
#pragma unroll
        for (int tm = 0; tm < 2; tm++) {
#pragma unroll
            for (int rr = 0; rr < 2; rr++) {
                int n = n0 + n0w + tm * 16 + rr * 8 + gid;
                if (n < N) {
#pragma unroll
                    for (int tn = 0; tn < 4; tn++) {
                        int c = cb + c0w + tn * 8 + qid * 2;
                        s[tn * 2 + 0] += tanhf(d[tm][tn][rr * 2 + 0] + bias[c]);
                        s[tn * 2 + 1] += tanhf(d[tm][tn][rr * 2 + 1] + bias[c + 1]);
                    }
                }
            }
        }
        __syncthreads();   // cs init visible
#pragma unroll
        for (int tn = 0; tn < 4; tn++) {
            atomicAdd(&cs[c0w + tn * 8 + qid * 2 + 0], s[tn * 2 + 0]);
            atomicAdd(&cs[c0w + tn * 8 + qid * 2 + 1], s[tn * 2 + 1]);
        }
        __syncthreads();
        if (t < 64) atomicAdd(&g_colsum[mode - 1][cb + t], (double)cs[t]);
    }
}

// ---------------- elem projection (tiny: 118 x 128, K=64) ----------------
__global__ void k_proj_elem(const float* __restrict__ x, const float* __restrict__ W,
                            const float* __restrict__ b)
{
    int i = blockIdx.x * blockDim.x + threadIdx.x;
    if (i >= NELEM * HIDC) return;
    int n = i >> 7, c = i & 127;
    float acc = b[c];
    const float* xr = x + n * 64;
    const float* wr = W + c * 64;
#pragma unroll 16
    for (int k = 0; k < 64; k++) acc += xr[k] * wr[k];
    g_hh_elem[i] = __float2half_rn(acc);
}

// ---------------- per-node attention coefficients (fp16 features) ----------
__global__ __launch_bounds__(256) void k_alphas_mat(
    const float* __restrict__ a_de, const float* __restrict__ a_sm,
    const float* __restrict__ a_dm)
{
    __shared__ float sa[3][128];
    int t = threadIdx.x;
    if (t < 128) {
        sa[0][t] = a_de[t]; sa[1][t] = a_sm[t]; sa[2][t] = a_dm[t];
    }
    __syncthreads();

    int i = blockIdx.x * blockDim.x + t;
    if (i >= NMAT * NH) return;
    int h = i & 7;
    const __half* hp = g_hh_mat + i * 16;   // i*16 == n*128 + h*16
    uint4 r0 = *(const uint4*)hp;           // 8 halfs
    uint4 r1 = *(const uint4*)(hp + 8);
    float hv[16];
    {
        unsigned rr[8] = {r0.x, r0.y, r0.z, r0.w, r1.x, r1.y, r1.z, r1.w};
#pragma unroll
        for (int k = 0; k < 8; k++) {
            float2 f = __half22float2(*(half2*)&rr[k]);
            hv[k * 2] = f.x; hv[k * 2 + 1] = f.y;
        }
    }
    float s1 = 0.f, s2 = 0.f, s3 = 0.f;
#pragma unroll
    for (int k = 0; k < 16; k++) {
        s1 += hv[k] * sa[0][h * 16 + k];
        s2 += hv[k] * sa[1][h * 16 + k];
        s3 += hv[k] * sa[2][h * 16 + k];
    }
    g_adst_em[i] = s1; g_asrc_mm[i] = s2; g_adst_mm[i] = s3;
}

__global__ void k_alphas_elem(const float* __restrict__ a_se)
{
    int i = blockIdx.x * blockDim.x + threadIdx.x;
    if (i >= NELEM * NH) return;
    int h = i & 7;
    const __half* hp = g_hh_elem + i * 16;
    float s = 0.f;
#pragma unroll
    for (int k = 0; k < 16; k++)
        s += __half2float(hp[k]) * __ldg(&a_se[h * 16 + k]);
    g_asrc_em[i] = s;
}

// ---------------- CSR aggregation: warp per (type,dst) row ----------------
__global__ __launch_bounds__(256) void k_agg()
{
    int gw = (blockIdx.x * blockDim.x + threadIdx.x) >> 5;   // flat (type,dst)
    int lane = threadIdx.x & 31;
    if (gw >= SCAN_N) return;
    int type = gw >= NMAT;
    int d = gw - type * NMAT;
    const float*  as = type ? g_asrc_mm : g_asrc_em;
    const float*  ad = type ? g_adst_mm : g_adst_em;
    const __half* xs = type ? g_hh_mat : g_hh_elem;
    int h = lane >> 2;
    float adh = ad[d * 8 + h];
    int start = g_base[gw];
    int deg = g_cnt[gw];
    float4 acc = make_float4(0.f, 0.f, 0.f, 0.f);
    float den = 0.f;
    int i = 0;
    for (; i + 4 <= deg; i += 4) {
        int s0 = g_sorted[start + i + 0];
        int s1 = g_sorted[start + i + 1];
        int s2 = g_sorted[start + i + 2];
        int s3 = g_sorted[start + i + 3];
        uint2 r0 = *(const uint2*)(xs + s0 * 128 + lane * 4);
        uint2 r1 = *(const uint2*)(xs + s1 * 128 + lane * 4);
        uint2 r2 = *(const uint2*)(xs + s2 * 128 + lane * 4);
        uint2 r3 = *(const uint2*)(xs + s3 * 128 + lane * 4);
        float a0 = __ldg(&as[s0 * 8 + h]) + adh;
        float a1 = __ldg(&as[s1 * 8 + h]) + adh;
        float a2 = __ldg(&as[s2 * 8 + h]) + adh;
        float a3 = __ldg(&as[s3 * 8 + h]) + adh;
        a0 = a0 > 0.f ? a0 : 0.2f * a0;
        a1 = a1 > 0.f ? a1 : 0.2f * a1;
        a2 = a2 > 0.f ? a2 : 0.2f * a2;
        a3 = a3 > 0.f ? a3 : 0.2f * a3;
        float e0 = __expf(a0), e1 = __expf(a1), e2 = __expf(a2), e3 = __expf(a3);
        den += (e0 + e1) + (e2 + e3);
        float2 x0a = __half22float2(*(half2*)&r0.x), x0b = __half22float2(*(half2*)&r0.y);
        float2 x1a = __half22float2(*(half2*)&r1.x), x1b = __half22float2(*(half2*)&r1.y);
        float2 x2a = __half22float2(*(half2*)&r2.x), x2b = __half22float2(*(half2*)&r2.y);
        float2 x3a = __half22float2(*(half2*)&r3.x), x3b = __half22float2(*(half2*)&r3.y);
        acc.x += (e0 * x0a.x + e1 * x1a.x) + (e2 * x2a.x + e3 * x3a.x);
        acc.y += (e0 * x0a.y + e1 * x1a.y) + (e2 * x2a.y + e3 * x3a.y);
        acc.z += (e0 * x0b.x + e1 * x1b.x) + (e2 * x2b.x + e3 * x3b.x);
        acc.w += (e0 * x0b.y + e1 * x1b.y) + (e2 * x2b.y + e3 * x3b.y);
    }
    for (; i < deg; i++) {
        int s0 = g_sorted[start + i];
        uint2 r0 = *(const uint2*)(xs + s0 * 128 + lane * 4);
        float a0 = __ldg(&as[s0 * 8 + h]) + adh;
        a0 = a0 > 0.f ? a0 : 0.2f * a0;
        float e0 = __expf(a0);
        den += e0;
        float2 x0a = __half22float2(*(half2*)&r0.x);
        float2 x0b = __half22float2(*(half2*)&r0.y);
        acc.x += e0 * x0a.x; acc.y += e0 * x0a.y;
        acc.z += e0 * x0b.x; acc.w += e0 * x0b.y;
    }
    float inv = 1.f / (den + 1e-16f);
    __half2 o01 = __float22half2_rn(make_float2(fmaxf(acc.x * inv, 0.f),
                                                fmaxf(acc.y * inv, 0.f)));
    __half2 o23 = __float22half2_rn(make_float2(fmaxf(acc.z * inv, 0.f),
                                                fmaxf(acc.w * inv, 0.f)));
    uint2 wv;
    wv.x = *(unsigned*)&o01; wv.y = *(unsigned*)&o23;
    *(uint2*)(((__half*)g_o) + (size_t)gw * 128 + lane * 4) = wv;
}

// ---------------- semantic attention over 2 metapaths ----------------
__global__ void k_semantic(const float* __restrict__ q)
{
    int t = threadIdx.x;  // 128
    float p0 = q[t] * (float)(g_colsum[0][t] * (1.0 / NMAT));
    float p1 = q[t] * (float)(g_colsum[1][t] * (1.0 / NMAT));
    for (int off = 16; off; off >>= 1) {
        p0 += __shfl_down_sync(0xffffffffu, p0, off);
        p1 += __shfl_down_sync(0xffffffffu, p1, off);
    }
    __shared__ float red[8];
    int w = t >> 5, l = t & 31;
    if (l == 0) { red[w * 2] = p0; red[w * 2 + 1] = p1; }
    __syncthreads();
    if (t == 0) {
        float s0 = red[0] + red[2] + red[4] + red[6];
        float s1 = red[1] + red[3] + red[5] + red[7];
        float m = fmaxf(s0, s1);
        float e0 = expf(s0 - m), e1 = expf(s1 - m);
        float inv = 1.f / (e0 + e1);
        g_attn[0] = e0 * inv; g_attn[1] = e1 * inv;
    }
}

// ---------------- final: out = (a0*o_em + a1*o_mm) @ Wl^T + bl ----------------
#define FIN_SMEM ((64 * 132 + 64 * 132) * 4)

__global__ __launch_bounds__(256) void k_final(
    const float* __restrict__ Wl, const float* __restrict__ bl,
    float* __restrict__ out, int N)
{
    extern __shared__ float sm[];
    float* ws = sm;                 // 64 x 132
    float* xs = sm + 64 * 132;      // 64 x 132
    float a0 = g_attn[0], a1 = g_attn[1];
    int n0 = blockIdx.x * 64;
    int t = threadIdx.x;

    for (int i = t; i < 64 * 32; i += 256) {
        int r = i >> 5, c4 = i & 31;
        *(float4*)&ws[r * 132 + c4 * 4] = ((const float4*)Wl)[i];
    }
    for (int i = t; i < 64 * 32; i += 256) {
        int r = i >> 5, c4 = i & 31;
        int n = n0 + r;
        float4 v = make_float4(0.f, 0.f, 0.f, 0.f);
        if (n < N) {
            uint2 ua = *(const uint2*)(g_o[0] + n * 128 + c4 * 4);
            uint2 ub = *(const uint2*)(g_o[1] + n * 128 + c4 * 4);
            float2 u01 = __half22float2(*(half2*)&ua.x);
            float2 u23 = __half22float2(*(half2*)&ua.y);
            float2 w01 = __half22float2(*(half2*)&ub.x);
            float2 w23 = __half22float2(*(half2*)&ub.y);
            v.x = a0 * u01.x + a1 * w01.x;
            v.y = a0 * u01.y + a1 * w01.y;
            v.z = a0 * u23.x + a1 * w23.x;
            v.w = a0 * u23.y + a1 * w23.y;
        }
        *(float4*)&xs[r * 132 + c4 * 4] = v;
    }
    __syncthreads();

    int cg = t & 15, ng = t >> 4;
    unsigned long long acc[4][4];
#pragma unroll
    for (int i = 0; i < 4; i++)
#pragma unroll
        for (int j = 0; j < 4; j++) acc[i][j] = 0ull;

    for (int k = 0; k < 128; k += 4) {
        ulonglong2 xv[4], wv[4];
#pragma unroll
        for (int i = 0; i < 4; i++)
            xv[i] = *(const ulonglong2*)&xs[(ng + 16 * i) * 132 + k];
#pragma unroll
        for (int j = 0; j < 4; j++)
            wv[j] = *(const ulonglong2*)&ws[(cg + 16 * j) * 132 + k];
#pragma unroll
        for (int i = 0; i < 4; i++)
#pragma unroll
            for (int j = 0; j < 4; j++) {
                FMA2(acc[i][j], xv[i].x, wv[j].x);
                FMA2(acc[i][j], xv[i].y, wv[j].y);
            }
    }
#pragma unroll
    for (int i = 0; i < 4; i++) {
        int n = n0 + ng + 16 * i;
        if (n < N) {
#pragma unroll
            for (int j = 0; j < 4; j++) {
                U2 u; u.u = acc[i][j];
                out[n * OUTC + cg + 16 * j] = u.f.x + u.f.y + bl[cg + 16 * j];
            }
        }
    }
}

// ---------------- launch ----------------
extern "C" void kernel_launch(void* const* d_in, const int* in_sizes, int n_in,
                              void* d_out, int out_size)
{
    const float* x_mat    = (const float*)d_in[0];
    const float* x_elem   = (const float*)d_in[1];
    const float* Wpm      = (const float*)d_in[2];
    const float* bpm      = (const float*)d_in[3];
    const float* Wpe      = (const float*)d_in[4];
    const float* bpe      = (const float*)d_in[5];
    const float* a_src_em = (const float*)d_in[6];
    const float* a_dst_em = (const float*)d_in[7];
    const float* a_src_mm = (const float*)d_in[8];
    const float* a_dst_mm = (const float*)d_in[9];
    const float* Wk       = (const float*)d_in[10];
    const float* bk       = (const float*)d_in[11];
    const float* q        = (const float*)d_in[12];
    const float* Wl       = (const float*)d_in[13];
    const float* bl       = (const float*)d_in[14];
    const int*   src_em   = (const int*)d_in[15];
    const int*   dst_em   = (const int*)d_in[16];
    const int*   src_mm   = (const int*)d_in[17];
    const int*   dst_mm   = (const int*)d_in[18];
    float* out = (float*)d_out;
    int E_em = in_sizes[15];
    int E_mm = in_sizes[17];

    cudaFuncSetAttribute(k_gemm_tc, cudaFuncAttributeMaxDynamicSharedMemorySize, TCG_SMEM);
    cudaFuncSetAttribute(k_final,   cudaFuncAttributeMaxDynamicSharedMemorySize, FIN_SMEM);

    int gb = (NMAT + 63) / 64;           // final-GEMM node blocks
    int tb = (NMAT + 127) / 128;         // tc-GEMM node blocks = 782
    int eg = 148 * 8;

    dim3 g0(tb, 2, 1);    // mode 0
    dim3 g12(tb, 2, 2);   // modes 1 and 2 merged

    k_init<<<256, 256>>>();                                             // 0
    k_count<<<eg, 256>>>(dst_em, E_em, dst_mm, E_mm);                   // 1
    k_scan1<<<NB, 256>>>();                                             // 2
    k_gemm_tc<<<g0, 256, TCG_SMEM>>>(x_mat, Wpm, bpm, NMAT, 0);         // 3  <- profiled
    k_scan2<<<1, 256>>>();                                              // 4
    k_scan3<<<(SCAN_N + 255) / 256, 256>>>();                           // 5
    k_scatter<<<eg, 256>>>(src_em, dst_em, E_em, src_mm, dst_mm, E_mm); // 6
    k_proj_elem<<<(NELEM * HIDC + 255) / 256, 256>>>(x_elem, Wpe, bpe); // 7
    k_alphas_mat<<<(NMAT * NH + 255) / 256, 256>>>(a_dst_em, a_src_mm, a_dst_mm);
    k_alphas_elem<<<(NELEM * NH + 255) / 256, 256>>>(a_src_em);
    k_agg<<<(SCAN_N * 32 + 255) / 256, 256>>>();
    k_gemm_tc<<<g12, 256, TCG_SMEM>>>(nullptr, Wk, bk, NMAT, 1);
    k_semantic<<<1, 128>>>(q);
    k_final<<<gb, 256, FIN_SMEM>>>(Wl, bl, out, NMAT);
}